// round 1
// baseline (speedup 1.0000x reference)
#include <cuda_runtime.h>
#include <cstdint>

#define B_ 2
#define S_ 2048
#define D_ 2048
#define H_ 16
#define HD_ 128
#define WINDOW_ 256
#define MTOT_ (B_ * S_)   // 4096

// -------- scratch (static __device__ arrays; no runtime allocation) --------
__device__ float g_Q[(size_t)MTOT_ * D_];
__device__ float g_K[(size_t)MTOT_ * D_];
__device__ float g_V[(size_t)MTOT_ * D_];
__device__ float g_AO[(size_t)MTOT_ * D_];

// ============================================================================
// SGEMM: C[M,N] = A[M,K] @ B[K,N] (+ optional bias[N])
// BM=BN=128, BK=16, 256 threads, 8x8 per-thread micro-tile, float4 everywhere.
// Requires M%128==0, N%128==0, K%16==0 (true for all 4 GEMMs here).
// ============================================================================
__global__ __launch_bounds__(256, 2)
void sgemm128(const float* __restrict__ A, const float* __restrict__ Bm,
              const float* __restrict__ bias, float* __restrict__ C,
              int M, int N, int K)
{
    __shared__ float As[16][128];
    __shared__ float Bs[16][128];

    const int tid  = threadIdx.x;
    const int trow = tid >> 4;   // 0..15
    const int tcol = tid & 15;   // 0..15
    const int m0   = blockIdx.y << 7;
    const int n0   = blockIdx.x << 7;

    float acc[8][8];
#pragma unroll
    for (int i = 0; i < 8; i++)
#pragma unroll
        for (int j = 0; j < 8; j++) acc[i][j] = 0.f;

    for (int k0 = 0; k0 < K; k0 += 16) {
        // ---- load A tile (128x16) transposed into As[k][m], B tile (16x128) ----
#pragma unroll
        for (int t = 0; t < 2; t++) {
            int f  = tid + (t << 8);          // 0..511 float4 slots
            int ar = f >> 2;                  // 0..127 (A row)
            int ac = (f & 3) << 2;            // 0,4,8,12 (A col group)
            float4 av = *(const float4*)(A + (size_t)(m0 + ar) * K + k0 + ac);
            As[ac + 0][ar] = av.x;
            As[ac + 1][ar] = av.y;
            As[ac + 2][ar] = av.z;
            As[ac + 3][ar] = av.w;

            int br = f >> 5;                  // 0..15 (B row)
            int bc = (f & 31) << 2;           // 0..124
            *(float4*)(&Bs[br][bc]) =
                *(const float4*)(Bm + (size_t)(k0 + br) * N + n0 + bc);
        }
        __syncthreads();

#pragma unroll
        for (int kk = 0; kk < 16; kk++) {
            float a[8], b[8];
            *(float4*)(a)     = *(const float4*)(&As[kk][trow * 8]);
            *(float4*)(a + 4) = *(const float4*)(&As[kk][trow * 8 + 4]);
            *(float4*)(b)     = *(const float4*)(&Bs[kk][tcol * 8]);
            *(float4*)(b + 4) = *(const float4*)(&Bs[kk][tcol * 8 + 4]);
#pragma unroll
            for (int i = 0; i < 8; i++)
#pragma unroll
                for (int j = 0; j < 8; j++)
                    acc[i][j] += a[i] * b[j];
        }
        __syncthreads();
    }

    // ---- epilogue ----
#pragma unroll
    for (int i = 0; i < 8; i++) {
        const int row = m0 + trow * 8 + i;
#pragma unroll
        for (int jq = 0; jq < 2; jq++) {
            const int col = n0 + tcol * 8 + jq * 4;
            float4 v;
            v.x = acc[i][jq * 4 + 0];
            v.y = acc[i][jq * 4 + 1];
            v.z = acc[i][jq * 4 + 2];
            v.w = acc[i][jq * 4 + 3];
            if (bias) {
                const float4 bv = *(const float4*)(bias + col);
                v.x += bv.x; v.y += bv.y; v.z += bv.z; v.w += bv.w;
            }
            *(float4*)(C + (size_t)row * N + col) = v;
        }
    }
}

// ============================================================================
// Banded (sliding-window) causal attention, flash-style online softmax.
// Block = (query tile of 64, b*H). 256 threads as 16x16:
//   thread (ty,tx): scores 4x4 tile of S(64x64); O rows ty*4..+3, cols tx*8..+7.
// Key chunks of 64 starting at max(0, q0-256) (aligned), masked per element.
// Row reductions via 16-lane shuffle groups (lanes sharing ty are contiguous).
// No softmax scaling (GPT-Neo: sqrt(hd) applied then divided out -> net 1).
// ============================================================================
#define QPAD 132   // 128 + 4 pad (keeps float4 alignment, kills bank conflicts)
#define SPAD 68

__global__ __launch_bounds__(256)
void attn_kernel(const int* __restrict__ amask)
{
    extern __shared__ float smf[];
    float* Qs  = smf;                    // [64][QPAD]
    float* KVs = smf + 64 * QPAD;        // [64][QPAD]  (K chunk, then V chunk)
    float* Ss  = smf + 2 * 64 * QPAD;    // [64][SPAD]  (P tile)

    const int tid  = threadIdx.x;
    const int ty   = tid >> 4;           // 0..15
    const int tx   = tid & 15;           // 0..15
    const int b    = blockIdx.y >> 4;    // H_ == 16
    const int h    = blockIdx.y & 15;
    const int q0   = blockIdx.x << 6;
    const int row0 = ty * 4;

    // ---- load Q tile (64 x 128) ----
    const float* Qg = g_Q + ((size_t)(b * S_ + q0)) * D_ + h * HD_;
#pragma unroll
    for (int t = 0; t < 8; t++) {
        int f  = tid + (t << 8);
        int r  = f >> 5;
        int dg = (f & 31) << 2;
        *(float4*)(&Qs[r * QPAD + dg]) = *(const float4*)(Qg + (size_t)r * D_ + dg);
    }

    float m_run[4], l_run[4], o[4][8];
#pragma unroll
    for (int i = 0; i < 4; i++) {
        m_run[i] = -1e30f;
        l_run[i] = 0.f;
#pragma unroll
        for (int c = 0; c < 8; c++) o[i][c] = 0.f;
    }

    int kbeg = q0 - WINDOW_;
    if (kbeg < 0) kbeg = 0;

    for (int k0 = kbeg; k0 <= q0; k0 += 64) {
        __syncthreads();   // previous PV done; Q tile visible (first iter)

        // ---- load K chunk ----
        const float* Kg = g_K + ((size_t)(b * S_ + k0)) * D_ + h * HD_;
#pragma unroll
        for (int t = 0; t < 8; t++) {
            int f  = tid + (t << 8);
            int r  = f >> 5;
            int dg = (f & 31) << 2;
            *(float4*)(&KVs[r * QPAD + dg]) = *(const float4*)(Kg + (size_t)r * D_ + dg);
        }
        __syncthreads();

        // ---- scores: s[i][j] = Q[row0+i] . K[tx*4+j] ----
        float s[4][4];
#pragma unroll
        for (int i = 0; i < 4; i++)
#pragma unroll
            for (int j = 0; j < 4; j++) s[i][j] = 0.f;

#pragma unroll 4
        for (int d = 0; d < HD_; d += 4) {
            float4 q4[4], k4[4];
#pragma unroll
            for (int i = 0; i < 4; i++)
                q4[i] = *(const float4*)(&Qs[(row0 + i) * QPAD + d]);
#pragma unroll
            for (int j = 0; j < 4; j++)
                k4[j] = *(const float4*)(&KVs[(tx * 4 + j) * QPAD + d]);
#pragma unroll
            for (int i = 0; i < 4; i++)
#pragma unroll
                for (int j = 0; j < 4; j++)
                    s[i][j] += q4[i].x * k4[j].x + q4[i].y * k4[j].y
                             + q4[i].z * k4[j].z + q4[i].w * k4[j].w;
        }

        // ---- mask (causal band + attention_mask) ----
#pragma unroll
        for (int j = 0; j < 4; j++) {
            const int kk = k0 + tx * 4 + j;
            const int am = amask[b * S_ + kk];
#pragma unroll
            for (int i = 0; i < 4; i++) {
                const int iq = q0 + row0 + i;
                const bool valid = (kk <= iq) && (iq - kk < WINDOW_) && (am > 0);
                if (!valid) s[i][j] = -1e30f;
            }
        }

        // ---- online softmax update (per row, 16-lane shuffle reduce) ----
#pragma unroll
        for (int i = 0; i < 4; i++) {
            float mc = fmaxf(fmaxf(s[i][0], s[i][1]), fmaxf(s[i][2], s[i][3]));
#pragma unroll
            for (int off = 8; off > 0; off >>= 1)
                mc = fmaxf(mc, __shfl_xor_sync(0xffffffffu, mc, off));
            const float mnew  = fmaxf(m_run[i], mc);
            const float scale = __expf(m_run[i] - mnew);   // 1 if both -1e30; 0 if m_run=-1e30
            m_run[i] = mnew;

            float lsum = 0.f;
#pragma unroll
            for (int j = 0; j < 4; j++) {
                // predicate-gated: masked entries contribute exactly 0 even if
                // mnew is still -1e30 (fully-masked rows in the first chunk)
                const float pv = (s[i][j] > -1e29f) ? __expf(s[i][j] - mnew) : 0.f;
                Ss[(row0 + i) * SPAD + tx * 4 + j] = pv;
                lsum += pv;
            }
#pragma unroll
            for (int off = 8; off > 0; off >>= 1)
                lsum += __shfl_xor_sync(0xffffffffu, lsum, off);
            l_run[i] = l_run[i] * scale + lsum;
#pragma unroll
            for (int c = 0; c < 8; c++) o[i][c] *= scale;
        }
        __syncthreads();   // scores consumed -> safe to overwrite KVs; Ss visible after next sync

        // ---- load V chunk (reuse KVs) ----
        const float* Vg = g_V + ((size_t)(b * S_ + k0)) * D_ + h * HD_;
#pragma unroll
        for (int t = 0; t < 8; t++) {
            int f  = tid + (t << 8);
            int r  = f >> 5;
            int dg = (f & 31) << 2;
            *(float4*)(&KVs[r * QPAD + dg]) = *(const float4*)(Vg + (size_t)r * D_ + dg);
        }
        __syncthreads();

        // ---- O += P @ V ----
#pragma unroll 8
        for (int j = 0; j < 64; j++) {
            float pv[4];
#pragma unroll
            for (int i = 0; i < 4; i++) pv[i] = Ss[(row0 + i) * SPAD + j];
            float v[8];
            *(float4*)(v)     = *(const float4*)(&KVs[j * QPAD + tx * 8]);
            *(float4*)(v + 4) = *(const float4*)(&KVs[j * QPAD + tx * 8 + 4]);
#pragma unroll
            for (int i = 0; i < 4; i++)
#pragma unroll
                for (int c = 0; c < 8; c++)
                    o[i][c] += pv[i] * v[c];
        }
    }

    // ---- normalize + store ----
    float* Og = g_AO + ((size_t)(b * S_ + q0)) * D_ + h * HD_;
#pragma unroll
    for (int i = 0; i < 4; i++) {
        const float inv = (l_run[i] > 0.f) ? (1.f / l_run[i]) : 0.f;
        float4 v0, v1;
        v0.x = o[i][0] * inv; v0.y = o[i][1] * inv;
        v0.z = o[i][2] * inv; v0.w = o[i][3] * inv;
        v1.x = o[i][4] * inv; v1.y = o[i][5] * inv;
        v1.z = o[i][6] * inv; v1.w = o[i][7] * inv;
        *(float4*)(Og + (size_t)(row0 + i) * D_ + tx * 8)     = v0;
        *(float4*)(Og + (size_t)(row0 + i) * D_ + tx * 8 + 4) = v1;
    }
}

// ============================================================================
// Launch
// ============================================================================
extern "C" void kernel_launch(void* const* d_in, const int* in_sizes, int n_in,
                              void* d_out, int out_size)
{
    const float* X  = (const float*)d_in[0];   // hidden_states [B,S,D]
    const int*   am = (const int*)  d_in[1];   // attention_mask [B,S]
    const float* Wq = (const float*)d_in[2];
    const float* Wk = (const float*)d_in[3];
    const float* Wv = (const float*)d_in[4];
    const float* Wo = (const float*)d_in[5];
    const float* bo = (const float*)d_in[6];
    float* out = (float*)d_out;

    float *Qp, *Kp, *Vp, *AOp;
    cudaGetSymbolAddress((void**)&Qp,  g_Q);
    cudaGetSymbolAddress((void**)&Kp,  g_K);
    cudaGetSymbolAddress((void**)&Vp,  g_V);
    cudaGetSymbolAddress((void**)&AOp, g_AO);

    const dim3 gg(D_ / 128, MTOT_ / 128);   // (16, 32)

    sgemm128<<<gg, 256>>>(X, Wq, nullptr, Qp, MTOT_, D_, D_);
    sgemm128<<<gg, 256>>>(X, Wk, nullptr, Kp, MTOT_, D_, D_);
    sgemm128<<<gg, 256>>>(X, Wv, nullptr, Vp, MTOT_, D_, D_);

    const size_t smem = (size_t)(2 * 64 * QPAD + 64 * SPAD) * sizeof(float); // 84992 B
    cudaFuncSetAttribute(attn_kernel,
                         cudaFuncAttributeMaxDynamicSharedMemorySize, (int)smem);
    attn_kernel<<<dim3(S_ / 64, B_ * H_), 256, smem>>>(am);

    sgemm128<<<gg, 256>>>(AOp, Wo, bo, out, MTOT_, D_, D_);
}

// round 3
// speedup vs baseline: 2.1008x; 2.1008x over previous
#include <cuda_runtime.h>
#include <cuda_bf16.h>
#include <cstdint>

#define B_ 2
#define S_ 2048
#define D_ 2048
#define H_ 16
#define HD_ 128
#define WINDOW_ 256
#define MTOT_ (B_ * S_)     // 4096
#define KDIM_ D_            // 2048

// -------- scratch (static __device__ arrays; no runtime allocation) --------
__device__ __align__(1024) float g_Q [(size_t)MTOT_ * D_];
__device__ __align__(1024) float g_K [(size_t)MTOT_ * D_];
__device__ __align__(1024) float g_V [(size_t)MTOT_ * D_];
__device__ __align__(1024) float g_AO[(size_t)MTOT_ * D_];

__device__ __align__(1024) __nv_bfloat16 g_Xhi [(size_t)MTOT_ * D_];
__device__ __align__(1024) __nv_bfloat16 g_Xlo [(size_t)MTOT_ * D_];
__device__ __align__(1024) __nv_bfloat16 g_AOhi[(size_t)MTOT_ * D_];
__device__ __align__(1024) __nv_bfloat16 g_AOlo[(size_t)MTOT_ * D_];
__device__ __align__(1024) __nv_bfloat16 g_Wqt_hi[(size_t)D_ * D_];
__device__ __align__(1024) __nv_bfloat16 g_Wqt_lo[(size_t)D_ * D_];
__device__ __align__(1024) __nv_bfloat16 g_Wkt_hi[(size_t)D_ * D_];
__device__ __align__(1024) __nv_bfloat16 g_Wkt_lo[(size_t)D_ * D_];
__device__ __align__(1024) __nv_bfloat16 g_Wvt_hi[(size_t)D_ * D_];
__device__ __align__(1024) __nv_bfloat16 g_Wvt_lo[(size_t)D_ * D_];
__device__ __align__(1024) __nv_bfloat16 g_Wot_hi[(size_t)D_ * D_];
__device__ __align__(1024) __nv_bfloat16 g_Wot_lo[(size_t)D_ * D_];

// ============================================================================
// helpers (generic PTX only — sm_80-compatible, safe for compute_103)
// ============================================================================
__device__ __forceinline__ uint32_t smem_u32(const void* p) {
    uint32_t a;
    asm("{ .reg .u64 t; cvta.to.shared.u64 t, %1; cvt.u32.u64 %0, t; }"
        : "=r"(a) : "l"(p));
    return a;
}

#define SWZ(o) ((o) ^ (((o) >> 3) & 0x70))

#define CP_ASYNC16(dst, src) \
    asm volatile("cp.async.cg.shared.global [%0], [%1], 16;" \
                 :: "r"(dst), "l"(src) : "memory")
#define CP_COMMIT() asm volatile("cp.async.commit_group;" ::: "memory")
#define CP_WAIT2()  asm volatile("cp.async.wait_group 2;" ::: "memory")

#define LDSM_X4(rr, addr) \
    asm volatile("ldmatrix.sync.aligned.m8n8.x4.shared.b16 {%0,%1,%2,%3}, [%4];" \
        : "=r"((rr)[0]), "=r"((rr)[1]), "=r"((rr)[2]), "=r"((rr)[3]) : "r"(addr))

#define MMA_BF16(cc, aa, b0, b1) \
    asm volatile("mma.sync.aligned.m16n8k16.row.col.f32.bf16.bf16.f32 " \
        "{%0,%1,%2,%3}, {%4,%5,%6,%7}, {%8,%9}, {%0,%1,%2,%3};" \
        : "+f"((cc)[0]), "+f"((cc)[1]), "+f"((cc)[2]), "+f"((cc)[3]) \
        : "r"((aa)[0]), "r"((aa)[1]), "r"((aa)[2]), "r"((aa)[3]), \
          "r"(b0), "r"(b1))

// ============================================================================
// bf16 3-split GEMM via mma.sync: C[4096,2048] = A[4096,2048] @ Bt[2048,2048]^T
// A = Ahi+Alo, B = Bhi+Blo (bf16 pairs); D = Ahi*Bhi + Ahi*Blo + Alo*Bhi (fp32)
// 128x128 CTA tile, BK=64, 4-stage cp.async pipeline, 8 warps (2x4).
// ============================================================================
#define BKB 128            // bytes per smem row (64 bf16)
#define STAGE_B 32768      // A(16KB) + B(16KB)
#define NCHUNKS 96         // 3 phases * 32 k-chunks
#define GEMM_SMEM (4 * STAGE_B)

struct GemmArgs {
    const __nv_bfloat16 *Ahi, *Alo, *Bhi, *Blo;
};

__device__ __forceinline__ void issue_chunk(
    const GemmArgs& ga, int t, int tid, int m0, int n0, uint32_t sb)
{
    const int p  = t >> 5;            // phase 0,1,2
    const int k0 = (t & 31) << 6;     // k offset (elements)
    const __nv_bfloat16* Ap = (p == 2) ? ga.Alo : ga.Ahi;
    const __nv_bfloat16* Bp = (p == 1) ? ga.Blo : ga.Bhi;
    const uint32_t stg = sb + (t & 3) * STAGE_B;
#pragma unroll
    for (int v = 0; v < 4; v++) {
        const int vec = tid + (v << 8);          // 0..1023
        const int row = vec >> 3;                // 0..127
        const int c16 = vec & 7;                 // 0..7 (16B cols)
        const uint32_t soff = SWZ(row * BKB + c16 * 16);
        const char* sa = (const char*)(Ap + (size_t)(m0 + row) * KDIM_ + k0) + c16 * 16;
        CP_ASYNC16(stg + soff, sa);
        const char* sbp = (const char*)(Bp + (size_t)(n0 + row) * KDIM_ + k0) + c16 * 16;
        CP_ASYNC16(stg + 16384 + soff, sbp);
    }
}

__global__ __launch_bounds__(256)
void gemm_bf16x3(GemmArgs ga, const float* __restrict__ bias,
                 float* __restrict__ C)
{
    extern __shared__ __align__(1024) char smg[];
    const uint32_t sb = smem_u32(smg);
    const int tid = threadIdx.x;
    const int wid = tid >> 5, lid = tid & 31;
    const int warp_m = wid & 1;        // 0..1  (64 rows each)
    const int warp_n = wid >> 1;       // 0..3  (32 cols each)
    const int m0 = blockIdx.y << 7;
    const int n0 = blockIdx.x << 7;

    const int grp = lid >> 3;          // ldmatrix lane group 0..3
    const int lr  = lid & 7;

    float c[4][4][4];
#pragma unroll
    for (int mt = 0; mt < 4; mt++)
#pragma unroll
        for (int nt = 0; nt < 4; nt++)
#pragma unroll
            for (int q = 0; q < 4; q++) c[mt][nt][q] = 0.f;

    // precompute (swizzle-free parts of) ldmatrix base row indices
    const int a_row_base = warp_m * 64 + lr + (grp & 1) * 8;   // + mt*16
    const int a_kb       = (grp >> 1) * 16;                    // + kt*32
    const int b_row_base = warp_n * 32 + lr + (grp >> 1) * 8;  // + np*16
    const int b_kb       = (grp & 1) * 16;                     // + kt*32

#pragma unroll
    for (int t = 0; t < 3; t++) { issue_chunk(ga, t, tid, m0, n0, sb); CP_COMMIT(); }

    for (int t = 0; t < NCHUNKS; t++) {
        CP_WAIT2();
        __syncthreads();
        if (t + 3 < NCHUNKS) issue_chunk(ga, t + 3, tid, m0, n0, sb);
        CP_COMMIT();

        const uint32_t As = sb + (t & 3) * STAGE_B;
        const uint32_t Bs = As + 16384;

#pragma unroll
        for (int kt = 0; kt < 4; kt++) {
            uint32_t a[4][4], b[2][4];
#pragma unroll
            for (int mt = 0; mt < 4; mt++) {
                const int row = a_row_base + mt * 16;
                LDSM_X4(a[mt], As + SWZ(row * BKB + kt * 32 + a_kb));
            }
#pragma unroll
            for (int np = 0; np < 2; np++) {
                const int nr = b_row_base + np * 16;
                LDSM_X4(b[np], Bs + SWZ(nr * BKB + kt * 32 + b_kb));
            }
#pragma unroll
            for (int mt = 0; mt < 4; mt++) {
#pragma unroll
                for (int np = 0; np < 2; np++) {
                    MMA_BF16(c[mt][np * 2],     a[mt], b[np][0], b[np][1]);
                    MMA_BF16(c[mt][np * 2 + 1], a[mt], b[np][2], b[np][3]);
                }
            }
        }
        __syncthreads();
    }

    // ---- epilogue ----
    const int l4 = lid >> 2;
    const int l2 = (lid & 3) << 1;
#pragma unroll
    for (int mt = 0; mt < 4; mt++) {
        const int row = m0 + warp_m * 64 + mt * 16 + l4;
#pragma unroll
        for (int nt = 0; nt < 4; nt++) {
            const int col = n0 + warp_n * 32 + nt * 8 + l2;
            float2 v0 = make_float2(c[mt][nt][0], c[mt][nt][1]);
            float2 v1 = make_float2(c[mt][nt][2], c[mt][nt][3]);
            if (bias) {
                const float b0 = bias[col], b1 = bias[col + 1];
                v0.x += b0; v0.y += b1;
                v1.x += b0; v1.y += b1;
            }
            *(float2*)(C + (size_t)row * D_ + col)       = v0;
            *(float2*)(C + (size_t)(row + 8) * D_ + col) = v1;
        }
    }
}

// ============================================================================
// fp32 -> (hi, lo) bf16 split, elementwise (vectorized x4)
// ============================================================================
__global__ void split_f32x4(const float4* __restrict__ in,
                            __nv_bfloat162* __restrict__ hi,
                            __nv_bfloat162* __restrict__ lo, int n4)
{
    int i = blockIdx.x * blockDim.x + threadIdx.x;
    if (i >= n4) return;
    float4 x = in[i];
    __nv_bfloat16 h0 = __float2bfloat16(x.x);
    __nv_bfloat16 h1 = __float2bfloat16(x.y);
    __nv_bfloat16 h2 = __float2bfloat16(x.z);
    __nv_bfloat16 h3 = __float2bfloat16(x.w);
    __nv_bfloat16 l0 = __float2bfloat16(x.x - __bfloat162float(h0));
    __nv_bfloat16 l1 = __float2bfloat16(x.y - __bfloat162float(h1));
    __nv_bfloat16 l2 = __float2bfloat16(x.z - __bfloat162float(h2));
    __nv_bfloat16 l3 = __float2bfloat16(x.w - __bfloat162float(h3));
    hi[2 * i]     = __halves2bfloat162(h0, h1);
    hi[2 * i + 1] = __halves2bfloat162(h2, h3);
    lo[2 * i]     = __halves2bfloat162(l0, l1);
    lo[2 * i + 1] = __halves2bfloat162(l2, l3);
}

// ============================================================================
// W[K, N] fp32 -> Wt_hi/lo[N, K] bf16 (transpose + split)
// ============================================================================
__global__ void transpose_split(const float* __restrict__ W,
                                __nv_bfloat16* __restrict__ hi,
                                __nv_bfloat16* __restrict__ lo)
{
    __shared__ float t[32][33];
    const int kt = blockIdx.y * 32, nt = blockIdx.x * 32;
    const int tx = threadIdx.x, ty = threadIdx.y;
#pragma unroll
    for (int i = 0; i < 32; i += 8)
        t[ty + i][tx] = W[(size_t)(kt + ty + i) * D_ + nt + tx];
    __syncthreads();
#pragma unroll
    for (int i = 0; i < 32; i += 8) {
        const float x = t[tx][ty + i];
        const size_t o = (size_t)(nt + ty + i) * KDIM_ + kt + tx;
        __nv_bfloat16 h = __float2bfloat16(x);
        hi[o] = h;
        lo[o] = __float2bfloat16(x - __bfloat162float(h));
    }
}

// ============================================================================
// Banded (sliding-window) causal attention — unchanged from R1 (552us)
// ============================================================================
#define QPAD 132
#define SPAD 68

__global__ __launch_bounds__(256)
void attn_kernel(const int* __restrict__ amask)
{
    extern __shared__ float smf[];
    float* Qs  = smf;
    float* KVs = smf + 64 * QPAD;
    float* Ss  = smf + 2 * 64 * QPAD;

    const int tid  = threadIdx.x;
    const int ty   = tid >> 4;
    const int tx   = tid & 15;
    const int b    = blockIdx.y >> 4;
    const int h    = blockIdx.y & 15;
    const int q0   = blockIdx.x << 6;
    const int row0 = ty * 4;

    const float* Qg = g_Q + ((size_t)(b * S_ + q0)) * D_ + h * HD_;
#pragma unroll
    for (int t = 0; t < 8; t++) {
        int f = tid + (t << 8);
        int r = f >> 5, dg = (f & 31) << 2;
        *(float4*)(&Qs[r * QPAD + dg]) = *(const float4*)(Qg + (size_t)r * D_ + dg);
    }

    float m_run[4], l_run[4], o[4][8];
#pragma unroll
    for (int i = 0; i < 4; i++) {
        m_run[i] = -1e30f; l_run[i] = 0.f;
#pragma unroll
        for (int c = 0; c < 8; c++) o[i][c] = 0.f;
    }

    int kbeg = q0 - WINDOW_;
    if (kbeg < 0) kbeg = 0;

    for (int k0 = kbeg; k0 <= q0; k0 += 64) {
        __syncthreads();
        const float* Kg = g_K + ((size_t)(b * S_ + k0)) * D_ + h * HD_;
#pragma unroll
        for (int t = 0; t < 8; t++) {
            int f = tid + (t << 8);
            int r = f >> 5, dg = (f & 31) << 2;
            *(float4*)(&KVs[r * QPAD + dg]) = *(const float4*)(Kg + (size_t)r * D_ + dg);
        }
        __syncthreads();

        float s[4][4];
#pragma unroll
        for (int i = 0; i < 4; i++)
#pragma unroll
            for (int j = 0; j < 4; j++) s[i][j] = 0.f;

#pragma unroll 4
        for (int d = 0; d < HD_; d += 4) {
            float4 q4[4], k4[4];
#pragma unroll
            for (int i = 0; i < 4; i++)
                q4[i] = *(const float4*)(&Qs[(row0 + i) * QPAD + d]);
#pragma unroll
            for (int j = 0; j < 4; j++)
                k4[j] = *(const float4*)(&KVs[(tx * 4 + j) * QPAD + d]);
#pragma unroll
            for (int i = 0; i < 4; i++)
#pragma unroll
                for (int j = 0; j < 4; j++)
                    s[i][j] += q4[i].x * k4[j].x + q4[i].y * k4[j].y
                             + q4[i].z * k4[j].z + q4[i].w * k4[j].w;
        }

#pragma unroll
        for (int j = 0; j < 4; j++) {
            const int kk = k0 + tx * 4 + j;
            const int am = amask[b * S_ + kk];
#pragma unroll
            for (int i = 0; i < 4; i++) {
                const int iq = q0 + row0 + i;
                const bool valid = (kk <= iq) && (iq - kk < WINDOW_) && (am > 0);
                if (!valid) s[i][j] = -1e30f;
            }
        }

#pragma unroll
        for (int i = 0; i < 4; i++) {
            float mc = fmaxf(fmaxf(s[i][0], s[i][1]), fmaxf(s[i][2], s[i][3]));
#pragma unroll
            for (int off = 8; off > 0; off >>= 1)
                mc = fmaxf(mc, __shfl_xor_sync(0xffffffffu, mc, off));
            const float mnew  = fmaxf(m_run[i], mc);
            const float scale = __expf(m_run[i] - mnew);
            m_run[i] = mnew;

            float lsum = 0.f;
#pragma unroll
            for (int j = 0; j < 4; j++) {
                const float pv = (s[i][j] > -1e29f) ? __expf(s[i][j] - mnew) : 0.f;
                Ss[(row0 + i) * SPAD + tx * 4 + j] = pv;
                lsum += pv;
            }
#pragma unroll
            for (int off = 8; off > 0; off >>= 1)
                lsum += __shfl_xor_sync(0xffffffffu, lsum, off);
            l_run[i] = l_run[i] * scale + lsum;
#pragma unroll
            for (int c = 0; c < 8; c++) o[i][c] *= scale;
        }
        __syncthreads();

        const float* Vg = g_V + ((size_t)(b * S_ + k0)) * D_ + h * HD_;
#pragma unroll
        for (int t = 0; t < 8; t++) {
            int f = tid + (t << 8);
            int r = f >> 5, dg = (f & 31) << 2;
            *(float4*)(&KVs[r * QPAD + dg]) = *(const float4*)(Vg + (size_t)r * D_ + dg);
        }
        __syncthreads();

#pragma unroll 8
        for (int j = 0; j < 64; j++) {
            float pv[4];
#pragma unroll
            for (int i = 0; i < 4; i++) pv[i] = Ss[(row0 + i) * SPAD + j];
            float v[8];
            *(float4*)(v)     = *(const float4*)(&KVs[j * QPAD + tx * 8]);
            *(float4*)(v + 4) = *(const float4*)(&KVs[j * QPAD + tx * 8 + 4]);
#pragma unroll
            for (int i = 0; i < 4; i++)
#pragma unroll
                for (int c = 0; c < 8; c++)
                    o[i][c] += pv[i] * v[c];
        }
    }

    float* Og = g_AO + ((size_t)(b * S_ + q0)) * D_ + h * HD_;
#pragma unroll
    for (int i = 0; i < 4; i++) {
        const float inv = (l_run[i] > 0.f) ? (1.f / l_run[i]) : 0.f;
        float4 v0, v1;
        v0.x = o[i][0]*inv; v0.y = o[i][1]*inv; v0.z = o[i][2]*inv; v0.w = o[i][3]*inv;
        v1.x = o[i][4]*inv; v1.y = o[i][5]*inv; v1.z = o[i][6]*inv; v1.w = o[i][7]*inv;
        *(float4*)(Og + (size_t)(row0 + i) * D_ + tx * 8)     = v0;
        *(float4*)(Og + (size_t)(row0 + i) * D_ + tx * 8 + 4) = v1;
    }
}

// ============================================================================
// Launch
// ============================================================================
extern "C" void kernel_launch(void* const* d_in, const int* in_sizes, int n_in,
                              void* d_out, int out_size)
{
    const float* X  = (const float*)d_in[0];
    const int*   am = (const int*)  d_in[1];
    const float* Wq = (const float*)d_in[2];
    const float* Wk = (const float*)d_in[3];
    const float* Wv = (const float*)d_in[4];
    const float* Wo = (const float*)d_in[5];
    const float* bo = (const float*)d_in[6];
    float* out = (float*)d_out;

    float *Qp, *Kp, *Vp, *AOp;
    cudaGetSymbolAddress((void**)&Qp,  g_Q);
    cudaGetSymbolAddress((void**)&Kp,  g_K);
    cudaGetSymbolAddress((void**)&Vp,  g_V);
    cudaGetSymbolAddress((void**)&AOp, g_AO);

    void *Xhi, *Xlo, *AOhi, *AOlo;
    void *Wqh, *Wql, *Wkh, *Wkl, *Wvh, *Wvl, *Woh, *Wol;
    cudaGetSymbolAddress(&Xhi,  g_Xhi);    cudaGetSymbolAddress(&Xlo,  g_Xlo);
    cudaGetSymbolAddress(&AOhi, g_AOhi);   cudaGetSymbolAddress(&AOlo, g_AOlo);
    cudaGetSymbolAddress(&Wqh,  g_Wqt_hi); cudaGetSymbolAddress(&Wql,  g_Wqt_lo);
    cudaGetSymbolAddress(&Wkh,  g_Wkt_hi); cudaGetSymbolAddress(&Wkl,  g_Wkt_lo);
    cudaGetSymbolAddress(&Wvh,  g_Wvt_hi); cudaGetSymbolAddress(&Wvl,  g_Wvt_lo);
    cudaGetSymbolAddress(&Woh,  g_Wot_hi); cudaGetSymbolAddress(&Wol,  g_Wot_lo);

    cudaFuncSetAttribute(gemm_bf16x3,
        cudaFuncAttributeMaxDynamicSharedMemorySize, GEMM_SMEM);
    const size_t asm_sz = (size_t)(2 * 64 * QPAD + 64 * SPAD) * sizeof(float);
    cudaFuncSetAttribute(attn_kernel,
        cudaFuncAttributeMaxDynamicSharedMemorySize, (int)asm_sz);

    // ---- conversions ----
    const int n4 = (MTOT_ * D_) / 4;
    split_f32x4<<<(n4 + 255) / 256, 256>>>(
        (const float4*)X, (__nv_bfloat162*)Xhi, (__nv_bfloat162*)Xlo, n4);
    const dim3 tg(D_ / 32, D_ / 32), tb(32, 8);
    transpose_split<<<tg, tb>>>(Wq, (__nv_bfloat16*)Wqh, (__nv_bfloat16*)Wql);
    transpose_split<<<tg, tb>>>(Wk, (__nv_bfloat16*)Wkh, (__nv_bfloat16*)Wkl);
    transpose_split<<<tg, tb>>>(Wv, (__nv_bfloat16*)Wvh, (__nv_bfloat16*)Wvl);
    transpose_split<<<tg, tb>>>(Wo, (__nv_bfloat16*)Woh, (__nv_bfloat16*)Wol);

    const dim3 gg(D_ / 128, MTOT_ / 128);  // (16, 32)
    GemmArgs gq = {(const __nv_bfloat16*)Xhi, (const __nv_bfloat16*)Xlo,
                   (const __nv_bfloat16*)Wqh, (const __nv_bfloat16*)Wql};
    GemmArgs gk = {(const __nv_bfloat16*)Xhi, (const __nv_bfloat16*)Xlo,
                   (const __nv_bfloat16*)Wkh, (const __nv_bfloat16*)Wkl};
    GemmArgs gv = {(const __nv_bfloat16*)Xhi, (const __nv_bfloat16*)Xlo,
                   (const __nv_bfloat16*)Wvh, (const __nv_bfloat16*)Wvl};
    gemm_bf16x3<<<gg, 256, GEMM_SMEM>>>(gq, nullptr, Qp);
    gemm_bf16x3<<<gg, 256, GEMM_SMEM>>>(gk, nullptr, Kp);
    gemm_bf16x3<<<gg, 256, GEMM_SMEM>>>(gv, nullptr, Vp);

    attn_kernel<<<dim3(S_ / 64, B_ * H_), 256, asm_sz>>>(am);

    split_f32x4<<<(n4 + 255) / 256, 256>>>(
        (const float4*)AOp, (__nv_bfloat162*)AOhi, (__nv_bfloat162*)AOlo, n4);
    GemmArgs go = {(const __nv_bfloat16*)AOhi, (const __nv_bfloat16*)AOlo,
                   (const __nv_bfloat16*)Woh, (const __nv_bfloat16*)Wol};
    gemm_bf16x3<<<gg, 256, GEMM_SMEM>>>(go, bo, out);
}

// round 4
// speedup vs baseline: 2.4472x; 1.1649x over previous
#include <cuda_runtime.h>
#include <cuda_bf16.h>
#include <cstdint>

#define B_ 2
#define S_ 2048
#define D_ 2048
#define H_ 16
#define HD_ 128
#define WINDOW_ 256
#define MTOT_ (B_ * S_)     // 4096
#define KDIM_ D_            // 2048

// -------- scratch (static __device__ arrays; no runtime allocation) --------
__device__ __align__(1024) float g_Q [(size_t)MTOT_ * D_];
__device__ __align__(1024) float g_K [(size_t)MTOT_ * D_];
__device__ __align__(1024) float g_V [(size_t)MTOT_ * D_];
__device__ __align__(1024) float g_AO[(size_t)MTOT_ * D_];

__device__ __align__(1024) __nv_bfloat16 g_Xhi [(size_t)MTOT_ * D_];
__device__ __align__(1024) __nv_bfloat16 g_Xlo [(size_t)MTOT_ * D_];
__device__ __align__(1024) __nv_bfloat16 g_AOhi[(size_t)MTOT_ * D_];
__device__ __align__(1024) __nv_bfloat16 g_AOlo[(size_t)MTOT_ * D_];
__device__ __align__(1024) __nv_bfloat16 g_Wqt_hi[(size_t)D_ * D_];
__device__ __align__(1024) __nv_bfloat16 g_Wqt_lo[(size_t)D_ * D_];
__device__ __align__(1024) __nv_bfloat16 g_Wkt_hi[(size_t)D_ * D_];
__device__ __align__(1024) __nv_bfloat16 g_Wkt_lo[(size_t)D_ * D_];
__device__ __align__(1024) __nv_bfloat16 g_Wvt_hi[(size_t)D_ * D_];
__device__ __align__(1024) __nv_bfloat16 g_Wvt_lo[(size_t)D_ * D_];
__device__ __align__(1024) __nv_bfloat16 g_Wot_hi[(size_t)D_ * D_];
__device__ __align__(1024) __nv_bfloat16 g_Wot_lo[(size_t)D_ * D_];

// ============================================================================
// helpers (generic PTX only — sm_80-compatible, safe for compute_103)
// ============================================================================
__device__ __forceinline__ uint32_t smem_u32(const void* p) {
    uint32_t a;
    asm("{ .reg .u64 t; cvta.to.shared.u64 t, %1; cvt.u32.u64 %0, t; }"
        : "=r"(a) : "l"(p));
    return a;
}

#define SWZ(o) ((o) ^ (((o) >> 3) & 0x70))

#define CP_ASYNC16(dst, src) \
    asm volatile("cp.async.cg.shared.global [%0], [%1], 16;" \
                 :: "r"(dst), "l"(src) : "memory")
#define CP_COMMIT() asm volatile("cp.async.commit_group;" ::: "memory")
#define CP_WAIT1()  asm volatile("cp.async.wait_group 1;" ::: "memory")

#define LDSM_X4(rr, addr) \
    asm volatile("ldmatrix.sync.aligned.m8n8.x4.shared.b16 {%0,%1,%2,%3}, [%4];" \
        : "=r"((rr)[0]), "=r"((rr)[1]), "=r"((rr)[2]), "=r"((rr)[3]) : "r"(addr))

#define MMA_BF16(cc, aa, b0, b1) \
    asm volatile("mma.sync.aligned.m16n8k16.row.col.f32.bf16.bf16.f32 " \
        "{%0,%1,%2,%3}, {%4,%5,%6,%7}, {%8,%9}, {%0,%1,%2,%3};" \
        : "+f"((cc)[0]), "+f"((cc)[1]), "+f"((cc)[2]), "+f"((cc)[3]) \
        : "r"((aa)[0]), "r"((aa)[1]), "r"((aa)[2]), "r"((aa)[3]), \
          "r"(b0), "r"(b1))

// ============================================================================
// bf16 3-split GEMM via mma.sync: C[4096,2048] = A[4096,2048] @ Bt[2048,2048]^T
// Combined-operand chunks: per k64 chunk load Ahi|Alo|Bhi|Blo (64KB stage) once,
// run all 3 split passes (hi*hi + hi*lo + lo*hi) from resident tiles.
// 128x128 CTA tile, BK=64, 3-stage cp.async pipeline, 8 warps (2x4).
// gridDim.z selects one of up to 3 (B, C) pairs (merged Q/K/V launch).
// ============================================================================
#define BKB 128            // bytes per smem row (64 bf16)
#define TILE_B 16384       // one 128x64 bf16 tile
#define STAGE_B 65536      // Ahi|Alo|Bhi|Blo
#define NCHUNKS 32         // K / 64
#define GEMM_SMEM (3 * STAGE_B)   // 196608

struct G3 {
    const __nv_bfloat16 *Ah, *Al;
    const __nv_bfloat16 *Bh0, *Bl0, *Bh1, *Bl1, *Bh2, *Bl2;
    float *C0, *C1, *C2;
    const float *bias;     // applied for z==0 only (O-GEMM path)
};

__device__ __forceinline__ void issue_chunk(
    const __nv_bfloat16* Ah, const __nv_bfloat16* Al,
    const __nv_bfloat16* Bh, const __nv_bfloat16* Bl,
    int t, int tid, int m0, int n0, uint32_t sb)
{
    const int k0 = t << 6;
    const uint32_t stg = sb + (t % 3) * STAGE_B;
#pragma unroll
    for (int v = 0; v < 4; v++) {
        const int vec = tid + (v << 8);          // 0..1023
        const int row = vec >> 3;                // 0..127
        const int c16 = vec & 7;                 // 0..7 (16B cols)
        const uint32_t soff = SWZ(row * BKB + c16 * 16);
        const size_t goA = (size_t)(m0 + row) * KDIM_ + k0;
        const size_t goB = (size_t)(n0 + row) * KDIM_ + k0;
        CP_ASYNC16(stg + soff,              (const char*)(Ah + goA) + c16 * 16);
        CP_ASYNC16(stg + TILE_B + soff,     (const char*)(Al + goA) + c16 * 16);
        CP_ASYNC16(stg + 2 * TILE_B + soff, (const char*)(Bh + goB) + c16 * 16);
        CP_ASYNC16(stg + 3 * TILE_B + soff, (const char*)(Bl + goB) + c16 * 16);
    }
}

__global__ __launch_bounds__(256)
void gemm_bf16x3(G3 ga)
{
    extern __shared__ __align__(1024) char smg[];
    const uint32_t sb = smem_u32(smg);
    const int tid = threadIdx.x;
    const int wid = tid >> 5, lid = tid & 31;
    const int warp_m = wid & 1;        // 0..1  (64 rows each)
    const int warp_n = wid >> 1;       // 0..3  (32 cols each)
    const int m0 = blockIdx.y << 7;
    const int n0 = blockIdx.x << 7;
    const int z  = blockIdx.z;

    const __nv_bfloat16* Bh = (z == 0) ? ga.Bh0 : (z == 1) ? ga.Bh1 : ga.Bh2;
    const __nv_bfloat16* Bl = (z == 0) ? ga.Bl0 : (z == 1) ? ga.Bl1 : ga.Bl2;
    float* C = (z == 0) ? ga.C0 : (z == 1) ? ga.C1 : ga.C2;
    const float* bias = (z == 0) ? ga.bias : nullptr;

    const int grp = lid >> 3;          // ldmatrix lane group 0..3
    const int lr  = lid & 7;

    float c[4][4][4];
#pragma unroll
    for (int mt = 0; mt < 4; mt++)
#pragma unroll
        for (int nt = 0; nt < 4; nt++)
#pragma unroll
            for (int q = 0; q < 4; q++) c[mt][nt][q] = 0.f;

    const int a_row_base = warp_m * 64 + lr + (grp & 1) * 8;   // + mt*16
    const int a_kb       = (grp >> 1) * 16;                    // + kt*32
    const int b_row_base = warp_n * 32 + lr + (grp >> 1) * 8;  // + np*16
    const int b_kb       = (grp & 1) * 16;                     // + kt*32

    issue_chunk(ga.Ah, ga.Al, Bh, Bl, 0, tid, m0, n0, sb); CP_COMMIT();
    issue_chunk(ga.Ah, ga.Al, Bh, Bl, 1, tid, m0, n0, sb); CP_COMMIT();

    for (int t = 0; t < NCHUNKS; t++) {
        CP_WAIT1();
        __syncthreads();
        if (t + 2 < NCHUNKS) {
            issue_chunk(ga.Ah, ga.Al, Bh, Bl, t + 2, tid, m0, n0, sb);
            CP_COMMIT();
        }

        const uint32_t Ahs = sb + (t % 3) * STAGE_B;
        const uint32_t Als = Ahs + TILE_B;
        const uint32_t Bhs = Ahs + 2 * TILE_B;
        const uint32_t Bls = Ahs + 3 * TILE_B;

#pragma unroll
        for (int kt = 0; kt < 4; kt++) {
            uint32_t ah[4][4], al[4][4], bh[2][4], bl[2][4];
#pragma unroll
            for (int mt = 0; mt < 4; mt++) {
                const uint32_t ao = SWZ((a_row_base + mt * 16) * BKB + kt * 32 + a_kb);
                LDSM_X4(ah[mt], Ahs + ao);
                LDSM_X4(al[mt], Als + ao);
            }
#pragma unroll
            for (int np = 0; np < 2; np++) {
                const uint32_t bo = SWZ((b_row_base + np * 16) * BKB + kt * 32 + b_kb);
                LDSM_X4(bh[np], Bhs + bo);
                LDSM_X4(bl[np], Bls + bo);
            }
#pragma unroll
            for (int mt = 0; mt < 4; mt++) {
#pragma unroll
                for (int np = 0; np < 2; np++) {
                    // hi*hi
                    MMA_BF16(c[mt][np * 2],     ah[mt], bh[np][0], bh[np][1]);
                    MMA_BF16(c[mt][np * 2 + 1], ah[mt], bh[np][2], bh[np][3]);
                    // hi*lo
                    MMA_BF16(c[mt][np * 2],     ah[mt], bl[np][0], bl[np][1]);
                    MMA_BF16(c[mt][np * 2 + 1], ah[mt], bl[np][2], bl[np][3]);
                    // lo*hi
                    MMA_BF16(c[mt][np * 2],     al[mt], bh[np][0], bh[np][1]);
                    MMA_BF16(c[mt][np * 2 + 1], al[mt], bh[np][2], bh[np][3]);
                }
            }
        }
        __syncthreads();
    }

    // ---- epilogue ----
    const int l4 = lid >> 2;
    const int l2 = (lid & 3) << 1;
#pragma unroll
    for (int mt = 0; mt < 4; mt++) {
        const int row = m0 + warp_m * 64 + mt * 16 + l4;
#pragma unroll
        for (int nt = 0; nt < 4; nt++) {
            const int col = n0 + warp_n * 32 + nt * 8 + l2;
            float2 v0 = make_float2(c[mt][nt][0], c[mt][nt][1]);
            float2 v1 = make_float2(c[mt][nt][2], c[mt][nt][3]);
            if (bias) {
                const float b0 = bias[col], b1 = bias[col + 1];
                v0.x += b0; v0.y += b1;
                v1.x += b0; v1.y += b1;
            }
            *(float2*)(C + (size_t)row * D_ + col)       = v0;
            *(float2*)(C + (size_t)(row + 8) * D_ + col) = v1;
        }
    }
}

// ============================================================================
// fp32 -> (hi, lo) bf16 split, elementwise (vectorized x4)
// ============================================================================
__global__ void split_f32x4(const float4* __restrict__ in,
                            __nv_bfloat162* __restrict__ hi,
                            __nv_bfloat162* __restrict__ lo, int n4)
{
    int i = blockIdx.x * blockDim.x + threadIdx.x;
    if (i >= n4) return;
    float4 x = in[i];
    __nv_bfloat16 h0 = __float2bfloat16(x.x);
    __nv_bfloat16 h1 = __float2bfloat16(x.y);
    __nv_bfloat16 h2 = __float2bfloat16(x.z);
    __nv_bfloat16 h3 = __float2bfloat16(x.w);
    __nv_bfloat16 l0 = __float2bfloat16(x.x - __bfloat162float(h0));
    __nv_bfloat16 l1 = __float2bfloat16(x.y - __bfloat162float(h1));
    __nv_bfloat16 l2 = __float2bfloat16(x.z - __bfloat162float(h2));
    __nv_bfloat16 l3 = __float2bfloat16(x.w - __bfloat162float(h3));
    hi[2 * i]     = __halves2bfloat162(h0, h1);
    hi[2 * i + 1] = __halves2bfloat162(h2, h3);
    lo[2 * i]     = __halves2bfloat162(l0, l1);
    lo[2 * i + 1] = __halves2bfloat162(l2, l3);
}

// ============================================================================
// W[K, N] fp32 -> Wt_hi/lo[N, K] bf16 (transpose + split); z selects matrix
// ============================================================================
__global__ void transpose_split4(const float* __restrict__ W0,
                                 const float* __restrict__ W1,
                                 const float* __restrict__ W2,
                                 const float* __restrict__ W3,
                                 __nv_bfloat16* __restrict__ h0, __nv_bfloat16* __restrict__ l0,
                                 __nv_bfloat16* __restrict__ h1, __nv_bfloat16* __restrict__ l1,
                                 __nv_bfloat16* __restrict__ h2, __nv_bfloat16* __restrict__ l2,
                                 __nv_bfloat16* __restrict__ h3, __nv_bfloat16* __restrict__ l3)
{
    const int z = blockIdx.z;
    const float* W = (z == 0) ? W0 : (z == 1) ? W1 : (z == 2) ? W2 : W3;
    __nv_bfloat16* hi = (z == 0) ? h0 : (z == 1) ? h1 : (z == 2) ? h2 : h3;
    __nv_bfloat16* lo = (z == 0) ? l0 : (z == 1) ? l1 : (z == 2) ? l2 : l3;

    __shared__ float t[32][33];
    const int kt = blockIdx.y * 32, nt = blockIdx.x * 32;
    const int tx = threadIdx.x, ty = threadIdx.y;
#pragma unroll
    for (int i = 0; i < 32; i += 8)
        t[ty + i][tx] = W[(size_t)(kt + ty + i) * D_ + nt + tx];
    __syncthreads();
#pragma unroll
    for (int i = 0; i < 32; i += 8) {
        const float x = t[tx][ty + i];
        const size_t o = (size_t)(nt + ty + i) * KDIM_ + kt + tx;
        __nv_bfloat16 h = __float2bfloat16(x);
        hi[o] = h;
        lo[o] = __float2bfloat16(x - __bfloat162float(h));
    }
}

// ============================================================================
// Banded (sliding-window) causal attention — + occupancy fix (regs<=128)
// ============================================================================
#define QPAD 132
#define SPAD 68

__global__ __launch_bounds__(256, 2)
void attn_kernel(const int* __restrict__ amask)
{
    extern __shared__ float smf[];
    float* Qs  = smf;
    float* KVs = smf + 64 * QPAD;
    float* Ss  = smf + 2 * 64 * QPAD;

    const int tid  = threadIdx.x;
    const int ty   = tid >> 4;
    const int tx   = tid & 15;
    const int b    = blockIdx.y >> 4;
    const int h    = blockIdx.y & 15;
    const int q0   = blockIdx.x << 6;
    const int row0 = ty * 4;

    const float* Qg = g_Q + ((size_t)(b * S_ + q0)) * D_ + h * HD_;
#pragma unroll
    for (int t = 0; t < 8; t++) {
        int f = tid + (t << 8);
        int r = f >> 5, dg = (f & 31) << 2;
        *(float4*)(&Qs[r * QPAD + dg]) = *(const float4*)(Qg + (size_t)r * D_ + dg);
    }

    float m_run[4], l_run[4], o[4][8];
#pragma unroll
    for (int i = 0; i < 4; i++) {
        m_run[i] = -1e30f; l_run[i] = 0.f;
#pragma unroll
        for (int c = 0; c < 8; c++) o[i][c] = 0.f;
    }

    int kbeg = q0 - WINDOW_;
    if (kbeg < 0) kbeg = 0;

    for (int k0 = kbeg; k0 <= q0; k0 += 64) {
        __syncthreads();
        const float* Kg = g_K + ((size_t)(b * S_ + k0)) * D_ + h * HD_;
#pragma unroll
        for (int t = 0; t < 8; t++) {
            int f = tid + (t << 8);
            int r = f >> 5, dg = (f & 31) << 2;
            *(float4*)(&KVs[r * QPAD + dg]) = *(const float4*)(Kg + (size_t)r * D_ + dg);
        }
        __syncthreads();

        float s[4][4];
#pragma unroll
        for (int i = 0; i < 4; i++)
#pragma unroll
            for (int j = 0; j < 4; j++) s[i][j] = 0.f;

#pragma unroll 4
        for (int d = 0; d < HD_; d += 4) {
            float4 q4[4], k4[4];
#pragma unroll
            for (int i = 0; i < 4; i++)
                q4[i] = *(const float4*)(&Qs[(row0 + i) * QPAD + d]);
#pragma unroll
            for (int j = 0; j < 4; j++)
                k4[j] = *(const float4*)(&KVs[(tx * 4 + j) * QPAD + d]);
#pragma unroll
            for (int i = 0; i < 4; i++)
#pragma unroll
                for (int j = 0; j < 4; j++)
                    s[i][j] += q4[i].x * k4[j].x + q4[i].y * k4[j].y
                             + q4[i].z * k4[j].z + q4[i].w * k4[j].w;
        }

#pragma unroll
        for (int j = 0; j < 4; j++) {
            const int kk = k0 + tx * 4 + j;
            const int am = amask[b * S_ + kk];
#pragma unroll
            for (int i = 0; i < 4; i++) {
                const int iq = q0 + row0 + i;
                const bool valid = (kk <= iq) && (iq - kk < WINDOW_) && (am > 0);
                if (!valid) s[i][j] = -1e30f;
            }
        }

#pragma unroll
        for (int i = 0; i < 4; i++) {
            float mc = fmaxf(fmaxf(s[i][0], s[i][1]), fmaxf(s[i][2], s[i][3]));
#pragma unroll
            for (int off = 8; off > 0; off >>= 1)
                mc = fmaxf(mc, __shfl_xor_sync(0xffffffffu, mc, off));
            const float mnew  = fmaxf(m_run[i], mc);
            const float scale = __expf(m_run[i] - mnew);
            m_run[i] = mnew;

            float lsum = 0.f;
#pragma unroll
            for (int j = 0; j < 4; j++) {
                const float pv = (s[i][j] > -1e29f) ? __expf(s[i][j] - mnew) : 0.f;
                Ss[(row0 + i) * SPAD + tx * 4 + j] = pv;
                lsum += pv;
            }
#pragma unroll
            for (int off = 8; off > 0; off >>= 1)
                lsum += __shfl_xor_sync(0xffffffffu, lsum, off);
            l_run[i] = l_run[i] * scale + lsum;
#pragma unroll
            for (int c = 0; c < 8; c++) o[i][c] *= scale;
        }
        __syncthreads();

        const float* Vg = g_V + ((size_t)(b * S_ + k0)) * D_ + h * HD_;
#pragma unroll
        for (int t = 0; t < 8; t++) {
            int f = tid + (t << 8);
            int r = f >> 5, dg = (f & 31) << 2;
            *(float4*)(&KVs[r * QPAD + dg]) = *(const float4*)(Vg + (size_t)r * D_ + dg);
        }
        __syncthreads();

#pragma unroll 8
        for (int j = 0; j < 64; j++) {
            float pv[4];
#pragma unroll
            for (int i = 0; i < 4; i++) pv[i] = Ss[(row0 + i) * SPAD + j];
            float v[8];
            *(float4*)(v)     = *(const float4*)(&KVs[j * QPAD + tx * 8]);
            *(float4*)(v + 4) = *(const float4*)(&KVs[j * QPAD + tx * 8 + 4]);
#pragma unroll
            for (int i = 0; i < 4; i++)
#pragma unroll
                for (int c = 0; c < 8; c++)
                    o[i][c] += pv[i] * v[c];
        }
    }

    float* Og = g_AO + ((size_t)(b * S_ + q0)) * D_ + h * HD_;
#pragma unroll
    for (int i = 0; i < 4; i++) {
        const float inv = (l_run[i] > 0.f) ? (1.f / l_run[i]) : 0.f;
        float4 v0, v1;
        v0.x = o[i][0]*inv; v0.y = o[i][1]*inv; v0.z = o[i][2]*inv; v0.w = o[i][3]*inv;
        v1.x = o[i][4]*inv; v1.y = o[i][5]*inv; v1.z = o[i][6]*inv; v1.w = o[i][7]*inv;
        *(float4*)(Og + (size_t)(row0 + i) * D_ + tx * 8)     = v0;
        *(float4*)(Og + (size_t)(row0 + i) * D_ + tx * 8 + 4) = v1;
    }
}

// ============================================================================
// Launch
// ============================================================================
extern "C" void kernel_launch(void* const* d_in, const int* in_sizes, int n_in,
                              void* d_out, int out_size)
{
    const float* X  = (const float*)d_in[0];
    const int*   am = (const int*)  d_in[1];
    const float* Wq = (const float*)d_in[2];
    const float* Wk = (const float*)d_in[3];
    const float* Wv = (const float*)d_in[4];
    const float* Wo = (const float*)d_in[5];
    const float* bo = (const float*)d_in[6];
    float* out = (float*)d_out;

    float *Qp, *Kp, *Vp, *AOp;
    cudaGetSymbolAddress((void**)&Qp,  g_Q);
    cudaGetSymbolAddress((void**)&Kp,  g_K);
    cudaGetSymbolAddress((void**)&Vp,  g_V);
    cudaGetSymbolAddress((void**)&AOp, g_AO);

    void *Xhi, *Xlo, *AOhi, *AOlo;
    void *Wqh, *Wql, *Wkh, *Wkl, *Wvh, *Wvl, *Woh, *Wol;
    cudaGetSymbolAddress(&Xhi,  g_Xhi);    cudaGetSymbolAddress(&Xlo,  g_Xlo);
    cudaGetSymbolAddress(&AOhi, g_AOhi);   cudaGetSymbolAddress(&AOlo, g_AOlo);
    cudaGetSymbolAddress(&Wqh,  g_Wqt_hi); cudaGetSymbolAddress(&Wql,  g_Wqt_lo);
    cudaGetSymbolAddress(&Wkh,  g_Wkt_hi); cudaGetSymbolAddress(&Wkl,  g_Wkt_lo);
    cudaGetSymbolAddress(&Wvh,  g_Wvt_hi); cudaGetSymbolAddress(&Wvl,  g_Wvt_lo);
    cudaGetSymbolAddress(&Woh,  g_Wot_hi); cudaGetSymbolAddress(&Wol,  g_Wot_lo);

    cudaFuncSetAttribute(gemm_bf16x3,
        cudaFuncAttributeMaxDynamicSharedMemorySize, GEMM_SMEM);
    const size_t asm_sz = (size_t)(2 * 64 * QPAD + 64 * SPAD) * sizeof(float);
    cudaFuncSetAttribute(attn_kernel,
        cudaFuncAttributeMaxDynamicSharedMemorySize, (int)asm_sz);

    // ---- conversions ----
    const int n4 = (MTOT_ * D_) / 4;
    split_f32x4<<<(n4 + 255) / 256, 256>>>(
        (const float4*)X, (__nv_bfloat162*)Xhi, (__nv_bfloat162*)Xlo, n4);
    transpose_split4<<<dim3(D_ / 32, D_ / 32, 4), dim3(32, 8)>>>(
        Wq, Wk, Wv, Wo,
        (__nv_bfloat16*)Wqh, (__nv_bfloat16*)Wql,
        (__nv_bfloat16*)Wkh, (__nv_bfloat16*)Wkl,
        (__nv_bfloat16*)Wvh, (__nv_bfloat16*)Wvl,
        (__nv_bfloat16*)Woh, (__nv_bfloat16*)Wol);

    // ---- merged Q/K/V GEMM (z = 0,1,2) ----
    G3 gqkv;
    gqkv.Ah = (const __nv_bfloat16*)Xhi;  gqkv.Al = (const __nv_bfloat16*)Xlo;
    gqkv.Bh0 = (const __nv_bfloat16*)Wqh; gqkv.Bl0 = (const __nv_bfloat16*)Wql;
    gqkv.Bh1 = (const __nv_bfloat16*)Wkh; gqkv.Bl1 = (const __nv_bfloat16*)Wkl;
    gqkv.Bh2 = (const __nv_bfloat16*)Wvh; gqkv.Bl2 = (const __nv_bfloat16*)Wvl;
    gqkv.C0 = Qp; gqkv.C1 = Kp; gqkv.C2 = Vp;
    gqkv.bias = nullptr;
    gemm_bf16x3<<<dim3(D_ / 128, MTOT_ / 128, 3), 256, GEMM_SMEM>>>(gqkv);

    attn_kernel<<<dim3(S_ / 64, B_ * H_), 256, asm_sz>>>(am);

    split_f32x4<<<(n4 + 255) / 256, 256>>>(
        (const float4*)AOp, (__nv_bfloat162*)AOhi, (__nv_bfloat162*)AOlo, n4);

    G3 go;
    go.Ah = (const __nv_bfloat16*)AOhi; go.Al = (const __nv_bfloat16*)AOlo;
    go.Bh0 = (const __nv_bfloat16*)Woh; go.Bl0 = (const __nv_bfloat16*)Wol;
    go.Bh1 = go.Bh0; go.Bl1 = go.Bl0; go.Bh2 = go.Bh0; go.Bl2 = go.Bl0;
    go.C0 = out; go.C1 = out; go.C2 = out;
    go.bias = bo;
    gemm_bf16x3<<<dim3(D_ / 128, MTOT_ / 128, 1), 256, GEMM_SMEM>>>(go);
}

// round 5
// speedup vs baseline: 3.4262x; 1.4001x over previous
#include <cuda_runtime.h>
#include <cuda_bf16.h>
#include <cstdint>

#define B_ 2
#define S_ 2048
#define D_ 2048
#define H_ 16
#define HD_ 128
#define WINDOW_ 256
#define MTOT_ (B_ * S_)     // 4096
#define KDIM_ D_            // 2048

// -------- scratch (static __device__ arrays; no runtime allocation) --------
__device__ __align__(1024) __nv_bfloat16 g_Xhi [(size_t)MTOT_ * D_];
__device__ __align__(1024) __nv_bfloat16 g_Xlo [(size_t)MTOT_ * D_];
__device__ __align__(1024) __nv_bfloat16 g_Qhi [(size_t)MTOT_ * D_];
__device__ __align__(1024) __nv_bfloat16 g_Qlo [(size_t)MTOT_ * D_];
__device__ __align__(1024) __nv_bfloat16 g_Khi [(size_t)MTOT_ * D_];
__device__ __align__(1024) __nv_bfloat16 g_Klo [(size_t)MTOT_ * D_];
__device__ __align__(1024) __nv_bfloat16 g_Vhi [(size_t)MTOT_ * D_];
__device__ __align__(1024) __nv_bfloat16 g_Vlo [(size_t)MTOT_ * D_];
__device__ __align__(1024) __nv_bfloat16 g_AOhi[(size_t)MTOT_ * D_];
__device__ __align__(1024) __nv_bfloat16 g_AOlo[(size_t)MTOT_ * D_];
__device__ __align__(1024) __nv_bfloat16 g_Wqt_hi[(size_t)D_ * D_];
__device__ __align__(1024) __nv_bfloat16 g_Wqt_lo[(size_t)D_ * D_];
__device__ __align__(1024) __nv_bfloat16 g_Wkt_hi[(size_t)D_ * D_];
__device__ __align__(1024) __nv_bfloat16 g_Wkt_lo[(size_t)D_ * D_];
__device__ __align__(1024) __nv_bfloat16 g_Wvt_hi[(size_t)D_ * D_];
__device__ __align__(1024) __nv_bfloat16 g_Wvt_lo[(size_t)D_ * D_];
__device__ __align__(1024) __nv_bfloat16 g_Wot_hi[(size_t)D_ * D_];
__device__ __align__(1024) __nv_bfloat16 g_Wot_lo[(size_t)D_ * D_];

// ============================================================================
// helpers (generic PTX only — sm_80-compatible, safe for compute_103)
// ============================================================================
__device__ __forceinline__ uint32_t smem_u32(const void* p) {
    uint32_t a;
    asm("{ .reg .u64 t; cvta.to.shared.u64 t, %1; cvt.u32.u64 %0, t; }"
        : "=r"(a) : "l"(p));
    return a;
}

#define SWZ(o) ((o) ^ (((o) >> 3) & 0x70))

#define CP_ASYNC16(dst, src) \
    asm volatile("cp.async.cg.shared.global [%0], [%1], 16;" \
                 :: "r"(dst), "l"(src) : "memory")
#define CP_COMMIT() asm volatile("cp.async.commit_group;" ::: "memory")
#define CP_WAIT0()  asm volatile("cp.async.wait_group 0;" ::: "memory")
#define CP_WAIT1()  asm volatile("cp.async.wait_group 1;" ::: "memory")

#define LDSM_X4(rr, addr) \
    asm volatile("ldmatrix.sync.aligned.m8n8.x4.shared.b16 {%0,%1,%2,%3}, [%4];" \
        : "=r"((rr)[0]), "=r"((rr)[1]), "=r"((rr)[2]), "=r"((rr)[3]) : "r"(addr))

#define LDSM_X4_T(rr, addr) \
    asm volatile("ldmatrix.sync.aligned.m8n8.x4.trans.shared.b16 {%0,%1,%2,%3}, [%4];" \
        : "=r"((rr)[0]), "=r"((rr)[1]), "=r"((rr)[2]), "=r"((rr)[3]) : "r"(addr))

#define MMA_BF16(cc, aa, b0, b1) \
    asm volatile("mma.sync.aligned.m16n8k16.row.col.f32.bf16.bf16.f32 " \
        "{%0,%1,%2,%3}, {%4,%5,%6,%7}, {%8,%9}, {%0,%1,%2,%3};" \
        : "+f"((cc)[0]), "+f"((cc)[1]), "+f"((cc)[2]), "+f"((cc)[3]) \
        : "r"((aa)[0]), "r"((aa)[1]), "r"((aa)[2]), "r"((aa)[3]), \
          "r"(b0), "r"(b1))

// pack two f32 into bf16x2: low half = lo, high half = hi
__device__ __forceinline__ uint32_t pack_bf16(float lo, float hi) {
    uint32_t r;
    asm("cvt.rn.bf16x2.f32 %0, %1, %2;" : "=r"(r) : "f"(hi), "f"(lo));
    return r;
}
__device__ __forceinline__ float2 unpack_bf16(uint32_t u) {
    __nv_bfloat162 b = *reinterpret_cast<__nv_bfloat162*>(&u);
    return make_float2(__bfloat162float(b.x), __bfloat162float(b.y));
}

// ============================================================================
// bf16 3-split GEMM via mma.sync (unchanged core from R4) with dual epilogue:
// fp32(+bias) OR split bf16 (hi/lo) outputs.
// ============================================================================
#define BKB 128
#define TILE_B 16384
#define STAGE_B 65536
#define NCHUNKS 32
#define GEMM_SMEM (3 * STAGE_B)

struct G3 {
    const __nv_bfloat16 *Ah, *Al;
    const __nv_bfloat16 *Bh0, *Bl0, *Bh1, *Bl1, *Bh2, *Bl2;
    __nv_bfloat16 *Ch0, *Cl0, *Ch1, *Cl1, *Ch2, *Cl2;   // split outputs
    float* Cf;                                           // fp32 output (z==0)
    const float* bias;
};

__device__ __forceinline__ void issue_chunk(
    const __nv_bfloat16* Ah, const __nv_bfloat16* Al,
    const __nv_bfloat16* Bh, const __nv_bfloat16* Bl,
    int t, int tid, int m0, int n0, uint32_t sb)
{
    const int k0 = t << 6;
    const uint32_t stg = sb + (t % 3) * STAGE_B;
#pragma unroll
    for (int v = 0; v < 4; v++) {
        const int vec = tid + (v << 8);
        const int row = vec >> 3;
        const int c16 = vec & 7;
        const uint32_t soff = SWZ(row * BKB + c16 * 16);
        const size_t goA = (size_t)(m0 + row) * KDIM_ + k0;
        const size_t goB = (size_t)(n0 + row) * KDIM_ + k0;
        CP_ASYNC16(stg + soff,              (const char*)(Ah + goA) + c16 * 16);
        CP_ASYNC16(stg + TILE_B + soff,     (const char*)(Al + goA) + c16 * 16);
        CP_ASYNC16(stg + 2 * TILE_B + soff, (const char*)(Bh + goB) + c16 * 16);
        CP_ASYNC16(stg + 3 * TILE_B + soff, (const char*)(Bl + goB) + c16 * 16);
    }
}

__global__ __launch_bounds__(256)
void gemm_bf16x3(G3 ga)
{
    extern __shared__ __align__(1024) char smg[];
    const uint32_t sb = smem_u32(smg);
    const int tid = threadIdx.x;
    const int wid = tid >> 5, lid = tid & 31;
    const int warp_m = wid & 1;
    const int warp_n = wid >> 1;
    const int m0 = blockIdx.y << 7;
    const int n0 = blockIdx.x << 7;
    const int z  = blockIdx.z;

    const __nv_bfloat16* Bh = (z == 0) ? ga.Bh0 : (z == 1) ? ga.Bh1 : ga.Bh2;
    const __nv_bfloat16* Bl = (z == 0) ? ga.Bl0 : (z == 1) ? ga.Bl1 : ga.Bl2;

    const int grp = lid >> 3;
    const int lr  = lid & 7;

    float c[4][4][4];
#pragma unroll
    for (int mt = 0; mt < 4; mt++)
#pragma unroll
        for (int nt = 0; nt < 4; nt++)
#pragma unroll
            for (int q = 0; q < 4; q++) c[mt][nt][q] = 0.f;

    const int a_row_base = warp_m * 64 + lr + (grp & 1) * 8;
    const int a_kb       = (grp >> 1) * 16;
    const int b_row_base = warp_n * 32 + lr + (grp >> 1) * 8;
    const int b_kb       = (grp & 1) * 16;

    issue_chunk(ga.Ah, ga.Al, Bh, Bl, 0, tid, m0, n0, sb); CP_COMMIT();
    issue_chunk(ga.Ah, ga.Al, Bh, Bl, 1, tid, m0, n0, sb); CP_COMMIT();

    for (int t = 0; t < NCHUNKS; t++) {
        CP_WAIT1();
        __syncthreads();
        if (t + 2 < NCHUNKS) {
            issue_chunk(ga.Ah, ga.Al, Bh, Bl, t + 2, tid, m0, n0, sb);
            CP_COMMIT();
        }

        const uint32_t Ahs = sb + (t % 3) * STAGE_B;
        const uint32_t Als = Ahs + TILE_B;
        const uint32_t Bhs = Ahs + 2 * TILE_B;
        const uint32_t Bls = Ahs + 3 * TILE_B;

#pragma unroll
        for (int kt = 0; kt < 4; kt++) {
            uint32_t ah[4][4], al[4][4], bh[2][4], bl[2][4];
#pragma unroll
            for (int mt = 0; mt < 4; mt++) {
                const uint32_t ao = SWZ((a_row_base + mt * 16) * BKB + kt * 32 + a_kb);
                LDSM_X4(ah[mt], Ahs + ao);
                LDSM_X4(al[mt], Als + ao);
            }
#pragma unroll
            for (int np = 0; np < 2; np++) {
                const uint32_t bo = SWZ((b_row_base + np * 16) * BKB + kt * 32 + b_kb);
                LDSM_X4(bh[np], Bhs + bo);
                LDSM_X4(bl[np], Bls + bo);
            }
#pragma unroll
            for (int mt = 0; mt < 4; mt++) {
#pragma unroll
                for (int np = 0; np < 2; np++) {
                    MMA_BF16(c[mt][np * 2],     ah[mt], bh[np][0], bh[np][1]);
                    MMA_BF16(c[mt][np * 2 + 1], ah[mt], bh[np][2], bh[np][3]);
                    MMA_BF16(c[mt][np * 2],     ah[mt], bl[np][0], bl[np][1]);
                    MMA_BF16(c[mt][np * 2 + 1], ah[mt], bl[np][2], bl[np][3]);
                    MMA_BF16(c[mt][np * 2],     al[mt], bh[np][0], bh[np][1]);
                    MMA_BF16(c[mt][np * 2 + 1], al[mt], bh[np][2], bh[np][3]);
                }
            }
        }
        __syncthreads();
    }

    // ---- epilogue ----
    const int l4 = lid >> 2;
    const int l2 = (lid & 3) << 1;
    if (ga.Cf) {
        float* C = ga.Cf;
#pragma unroll
        for (int mt = 0; mt < 4; mt++) {
            const int row = m0 + warp_m * 64 + mt * 16 + l4;
#pragma unroll
            for (int nt = 0; nt < 4; nt++) {
                const int col = n0 + warp_n * 32 + nt * 8 + l2;
                float2 v0 = make_float2(c[mt][nt][0], c[mt][nt][1]);
                float2 v1 = make_float2(c[mt][nt][2], c[mt][nt][3]);
                const float b0 = ga.bias[col], b1 = ga.bias[col + 1];
                v0.x += b0; v0.y += b1;
                v1.x += b0; v1.y += b1;
                *(float2*)(C + (size_t)row * D_ + col)       = v0;
                *(float2*)(C + (size_t)(row + 8) * D_ + col) = v1;
            }
        }
    } else {
        __nv_bfloat16* Ch = (z == 0) ? ga.Ch0 : (z == 1) ? ga.Ch1 : ga.Ch2;
        __nv_bfloat16* Cl = (z == 0) ? ga.Cl0 : (z == 1) ? ga.Cl1 : ga.Cl2;
#pragma unroll
        for (int mt = 0; mt < 4; mt++) {
            const int row = m0 + warp_m * 64 + mt * 16 + l4;
#pragma unroll
            for (int nt = 0; nt < 4; nt++) {
                const int col = n0 + warp_n * 32 + nt * 8 + l2;
                const size_t o0 = (size_t)row * D_ + col;
                const size_t o1 = (size_t)(row + 8) * D_ + col;
                uint32_t h0 = pack_bf16(c[mt][nt][0], c[mt][nt][1]);
                uint32_t h1 = pack_bf16(c[mt][nt][2], c[mt][nt][3]);
                float2 f0 = unpack_bf16(h0), f1 = unpack_bf16(h1);
                uint32_t l0p = pack_bf16(c[mt][nt][0] - f0.x, c[mt][nt][1] - f0.y);
                uint32_t l1p = pack_bf16(c[mt][nt][2] - f1.x, c[mt][nt][3] - f1.y);
                *(uint32_t*)(Ch + o0) = h0;
                *(uint32_t*)(Ch + o1) = h1;
                *(uint32_t*)(Cl + o0) = l0p;
                *(uint32_t*)(Cl + o1) = l1p;
            }
        }
    }
}

// ============================================================================
// fp32 -> (hi, lo) bf16 split, elementwise (vectorized x4)
// ============================================================================
__global__ void split_f32x4(const float4* __restrict__ in,
                            __nv_bfloat162* __restrict__ hi,
                            __nv_bfloat162* __restrict__ lo, int n4)
{
    int i = blockIdx.x * blockDim.x + threadIdx.x;
    if (i >= n4) return;
    float4 x = in[i];
    __nv_bfloat16 h0 = __float2bfloat16(x.x);
    __nv_bfloat16 h1 = __float2bfloat16(x.y);
    __nv_bfloat16 h2 = __float2bfloat16(x.z);
    __nv_bfloat16 h3 = __float2bfloat16(x.w);
    __nv_bfloat16 l0 = __float2bfloat16(x.x - __bfloat162float(h0));
    __nv_bfloat16 l1 = __float2bfloat16(x.y - __bfloat162float(h1));
    __nv_bfloat16 l2 = __float2bfloat16(x.z - __bfloat162float(h2));
    __nv_bfloat16 l3 = __float2bfloat16(x.w - __bfloat162float(h3));
    hi[2 * i]     = __halves2bfloat162(h0, h1);
    hi[2 * i + 1] = __halves2bfloat162(h2, h3);
    lo[2 * i]     = __halves2bfloat162(l0, l1);
    lo[2 * i + 1] = __halves2bfloat162(l2, l3);
}

// ============================================================================
// W[K, N] fp32 -> Wt_hi/lo[N, K] bf16 (transpose + split); z selects matrix
// ============================================================================
__global__ void transpose_split4(const float* __restrict__ W0,
                                 const float* __restrict__ W1,
                                 const float* __restrict__ W2,
                                 const float* __restrict__ W3,
                                 __nv_bfloat16* __restrict__ h0, __nv_bfloat16* __restrict__ l0,
                                 __nv_bfloat16* __restrict__ h1, __nv_bfloat16* __restrict__ l1,
                                 __nv_bfloat16* __restrict__ h2, __nv_bfloat16* __restrict__ l2,
                                 __nv_bfloat16* __restrict__ h3, __nv_bfloat16* __restrict__ l3)
{
    const int z = blockIdx.z;
    const float* W = (z == 0) ? W0 : (z == 1) ? W1 : (z == 2) ? W2 : W3;
    __nv_bfloat16* hi = (z == 0) ? h0 : (z == 1) ? h1 : (z == 2) ? h2 : h3;
    __nv_bfloat16* lo = (z == 0) ? l0 : (z == 1) ? l1 : (z == 2) ? l2 : l3;

    __shared__ float t[32][33];
    const int kt = blockIdx.y * 32, nt = blockIdx.x * 32;
    const int tx = threadIdx.x, ty = threadIdx.y;
#pragma unroll
    for (int i = 0; i < 32; i += 8)
        t[ty + i][tx] = W[(size_t)(kt + ty + i) * D_ + nt + tx];
    __syncthreads();
#pragma unroll
    for (int i = 0; i < 32; i += 8) {
        const float x = t[tx][ty + i];
        const size_t o = (size_t)(nt + ty + i) * KDIM_ + kt + tx;
        __nv_bfloat16 h = __float2bfloat16(x);
        hi[o] = h;
        lo[o] = __float2bfloat16(x - __bfloat162float(h));
    }
}

// ============================================================================
// Tensor-core banded attention. CTA = 64-query tile x (b,h), 4 warps.
// S = 3-split QK^T (mma.sync), online softmax in C-fragment registers,
// PV = Phi*Vhi + Phi*Vlo + Plo*Vhi with V via ldmatrix.trans.
// Writes AOhi/AOlo (bf16 split) directly.
// smem: Qhi|Qlo|Khi|Klo|Vhi|Vlo (6 x 16KB, each = 2 half-d tiles 64x64) + amask
// ============================================================================
#define AQHI 0
#define AQLO 16384
#define AKHI 32768
#define AKLO 49152
#define AVHI 65536
#define AVLO 81920
#define AAM  98304
#define ATT_SMEM (98304 + 256)

// load a 64-row x 128-col bf16 tile (row stride D_) into two swizzled 64x64 tiles
__device__ __forceinline__ void load64x128(uint32_t dst, const __nv_bfloat16* src, int tid)
{
#pragma unroll
    for (int v = 0; v < 8; v++) {
        const int idx = (v << 7) + tid;      // 0..1023
        const int row = idx >> 4;
        const int c16 = idx & 15;
        CP_ASYNC16(dst + ((c16 >> 3) << 13) + SWZ(row * 128 + (c16 & 7) * 16),
                   (const char*)(src + (size_t)row * D_) + c16 * 16);
    }
}

__global__ __launch_bounds__(128)
void attn_mma(const int* __restrict__ amask)
{
    extern __shared__ __align__(1024) char sma[];
    const uint32_t sb = smem_u32(sma);
    int* am_s = (int*)(sma + AAM);

    const int tid = threadIdx.x;
    const int w   = tid >> 5;
    const int lid = tid & 31;
    const int b   = blockIdx.y >> 4;
    const int h   = blockIdx.y & 15;
    const int q0  = blockIdx.x << 6;
    const int bS  = b * S_;

    const int grp = lid >> 3, lr = lid & 7;
    const int qr  = lid >> 2;          // quad row 0..7
    const int qc  = (lid & 3) << 1;    // 0,2,4,6

    // ---- prologue loads: Q + K(0) (group 1), V(0) (group 2) ----
    const size_t qoff = (size_t)(bS + q0) * D_ + h * HD_;
    load64x128(sb + AQHI, g_Qhi + qoff, tid);
    load64x128(sb + AQLO, g_Qlo + qoff, tid);
    int kbeg = q0 - WINDOW_;
    if (kbeg < 0) kbeg = 0;
    const int nch = ((q0 - kbeg) >> 6) + 1;
    const size_t koff0 = (size_t)(bS + kbeg) * D_ + h * HD_;
    load64x128(sb + AKHI, g_Khi + koff0, tid);
    load64x128(sb + AKLO, g_Klo + koff0, tid);
    CP_COMMIT();
    load64x128(sb + AVHI, g_Vhi + koff0, tid);
    load64x128(sb + AVLO, g_Vlo + koff0, tid);
    CP_COMMIT();

    float m0 = -1e30f, m1 = -1e30f, l0 = 0.f, l1 = 0.f;
    float co[16][4];
#pragma unroll
    for (int i = 0; i < 16; i++)
#pragma unroll
        for (int q = 0; q < 4; q++) co[i][q] = 0.f;

    const int r0g = q0 + w * 16 + qr;   // global q row (within batch seq)
    const int r1g = r0g + 8;

    const int arow = w * 16 + (grp & 1) * 8 + lr;   // Q fragment row
    const int brow = (grp >> 1) * 8 + lr;            // K fragment row base

    for (int ci = 0; ci < nch; ci++) {
        const int k0 = kbeg + (ci << 6);
        if (tid < 64) am_s[tid] = amask[bS + k0 + tid];
        CP_WAIT1();          // K(ci) (and Q) ready
        __syncthreads();

        // ---- scores: S[64q x 64kv] via 3-split ----
        float cs[8][4];
#pragma unroll
        for (int nt = 0; nt < 8; nt++)
#pragma unroll
            for (int q = 0; q < 4; q++) cs[nt][q] = 0.f;

#pragma unroll
        for (int ks = 0; ks < 8; ks++) {
            const uint32_t ao = ((ks >> 2) << 13)
                              + SWZ(arow * 128 + (ks & 3) * 32 + (grp >> 1) * 16);
            uint32_t ah[4], al[4];
            LDSM_X4(ah, sb + AQHI + ao);
            LDSM_X4(al, sb + AQLO + ao);
            const uint32_t bw = (ks & 3) * 32 + (grp & 1) * 16;
#pragma unroll
            for (int nb = 0; nb < 4; nb++) {
                const uint32_t bo = ((ks >> 2) << 13)
                                  + SWZ((brow + nb * 16) * 128 + bw);
                uint32_t bh[4], bl[4];
                LDSM_X4(bh, sb + AKHI + bo);
                LDSM_X4(bl, sb + AKLO + bo);
                MMA_BF16(cs[2 * nb],     ah, bh[0], bh[1]);
                MMA_BF16(cs[2 * nb + 1], ah, bh[2], bh[3]);
                MMA_BF16(cs[2 * nb],     ah, bl[0], bl[1]);
                MMA_BF16(cs[2 * nb + 1], ah, bl[2], bl[3]);
                MMA_BF16(cs[2 * nb],     al, bh[0], bh[1]);
                MMA_BF16(cs[2 * nb + 1], al, bh[2], bh[3]);
            }
        }

        // ---- mask ----
#pragma unroll
        for (int nt = 0; nt < 8; nt++) {
            const int cl = nt * 8 + qc;           // col within chunk
            const int c0 = k0 + cl, c1 = c0 + 1;
            const int am0 = am_s[cl], am1 = am_s[cl + 1];
            if (!(c0 <= r0g && r0g - c0 < WINDOW_ && am0)) cs[nt][0] = -1e30f;
            if (!(c1 <= r0g && r0g - c1 < WINDOW_ && am1)) cs[nt][1] = -1e30f;
            if (!(c0 <= r1g && r1g - c0 < WINDOW_ && am0)) cs[nt][2] = -1e30f;
            if (!(c1 <= r1g && r1g - c1 < WINDOW_ && am1)) cs[nt][3] = -1e30f;
        }

        // ---- online softmax (rows r0g, r1g; quad = 4 lanes per row) ----
        float mc0 = -1e30f, mc1 = -1e30f;
#pragma unroll
        for (int nt = 0; nt < 8; nt++) {
            mc0 = fmaxf(mc0, fmaxf(cs[nt][0], cs[nt][1]));
            mc1 = fmaxf(mc1, fmaxf(cs[nt][2], cs[nt][3]));
        }
        mc0 = fmaxf(mc0, __shfl_xor_sync(0xffffffffu, mc0, 1));
        mc0 = fmaxf(mc0, __shfl_xor_sync(0xffffffffu, mc0, 2));
        mc1 = fmaxf(mc1, __shfl_xor_sync(0xffffffffu, mc1, 1));
        mc1 = fmaxf(mc1, __shfl_xor_sync(0xffffffffu, mc1, 2));
        const float mn0 = fmaxf(m0, mc0), mn1 = fmaxf(m1, mc1);
        const float sc0 = __expf(m0 - mn0), sc1 = __expf(m1 - mn1);

        float ls0 = 0.f, ls1 = 0.f;
#pragma unroll
        for (int nt = 0; nt < 8; nt++) {
            cs[nt][0] = (cs[nt][0] > -1e29f) ? __expf(cs[nt][0] - mn0) : 0.f;
            cs[nt][1] = (cs[nt][1] > -1e29f) ? __expf(cs[nt][1] - mn0) : 0.f;
            cs[nt][2] = (cs[nt][2] > -1e29f) ? __expf(cs[nt][2] - mn1) : 0.f;
            cs[nt][3] = (cs[nt][3] > -1e29f) ? __expf(cs[nt][3] - mn1) : 0.f;
            ls0 += cs[nt][0] + cs[nt][1];
            ls1 += cs[nt][2] + cs[nt][3];
        }
        ls0 += __shfl_xor_sync(0xffffffffu, ls0, 1);
        ls0 += __shfl_xor_sync(0xffffffffu, ls0, 2);
        ls1 += __shfl_xor_sync(0xffffffffu, ls1, 1);
        ls1 += __shfl_xor_sync(0xffffffffu, ls1, 2);
        l0 = l0 * sc0 + ls0;
        l1 = l1 * sc1 + ls1;
#pragma unroll
        for (int i = 0; i < 16; i++) {
            co[i][0] *= sc0; co[i][1] *= sc0;
            co[i][2] *= sc1; co[i][3] *= sc1;
        }
        m0 = mn0; m1 = mn1;

        CP_WAIT0();          // V(ci) ready; everyone done with K(ci)
        __syncthreads();
        if (ci + 1 < nch) {  // prefetch K(ci+1) over PV compute
            const size_t kn = (size_t)(bS + k0 + 64) * D_ + h * HD_;
            load64x128(sb + AKHI, g_Khi + kn, tid);
            load64x128(sb + AKLO, g_Klo + kn, tid);
            CP_COMMIT();
        }

        // ---- PV: O += P @ V ----
#pragma unroll
        for (int ks = 0; ks < 4; ks++) {
            uint32_t phi[4], plo[4];
            phi[0] = pack_bf16(cs[2 * ks][0],     cs[2 * ks][1]);
            phi[1] = pack_bf16(cs[2 * ks][2],     cs[2 * ks][3]);
            phi[2] = pack_bf16(cs[2 * ks + 1][0], cs[2 * ks + 1][1]);
            phi[3] = pack_bf16(cs[2 * ks + 1][2], cs[2 * ks + 1][3]);
            {
                float2 f0 = unpack_bf16(phi[0]);
                float2 f1 = unpack_bf16(phi[1]);
                float2 f2 = unpack_bf16(phi[2]);
                float2 f3 = unpack_bf16(phi[3]);
                plo[0] = pack_bf16(cs[2*ks][0]   - f0.x, cs[2*ks][1]   - f0.y);
                plo[1] = pack_bf16(cs[2*ks][2]   - f1.x, cs[2*ks][3]   - f1.y);
                plo[2] = pack_bf16(cs[2*ks+1][0] - f2.x, cs[2*ks+1][1] - f2.y);
                plo[3] = pack_bf16(cs[2*ks+1][2] - f3.x, cs[2*ks+1][3] - f3.y);
            }
            const int vrow = ks * 16 + (grp & 1) * 8 + lr;
            const uint32_t vw = (grp >> 1) * 16;
#pragma unroll
            for (int g2 = 0; g2 < 8; g2++) {
                const uint32_t vo = ((g2 >> 2) << 13)
                                  + SWZ(vrow * 128 + (g2 & 3) * 32 + vw);
                uint32_t vh[4], vl[4];
                LDSM_X4_T(vh, sb + AVHI + vo);
                LDSM_X4_T(vl, sb + AVLO + vo);
                MMA_BF16(co[2 * g2],     phi, vh[0], vh[1]);
                MMA_BF16(co[2 * g2 + 1], phi, vh[2], vh[3]);
                MMA_BF16(co[2 * g2],     phi, vl[0], vl[1]);
                MMA_BF16(co[2 * g2 + 1], phi, vl[2], vl[3]);
                MMA_BF16(co[2 * g2],     plo, vh[0], vh[1]);
                MMA_BF16(co[2 * g2 + 1], plo, vh[2], vh[3]);
            }
        }
        __syncthreads();     // all warps done reading V(ci)
        if (ci + 1 < nch) {  // prefetch V(ci+1)
            const size_t vn = (size_t)(bS + k0 + 64) * D_ + h * HD_;
            load64x128(sb + AVHI, g_Vhi + vn, tid);
            load64x128(sb + AVLO, g_Vlo + vn, tid);
            CP_COMMIT();
        }
    }

    // ---- normalize + split-store AO ----
    const float inv0 = (l0 > 0.f) ? (1.f / l0) : 0.f;
    const float inv1 = (l1 > 0.f) ? (1.f / l1) : 0.f;
    const size_t row0 = (size_t)(bS + r0g) * D_;
    const size_t row1 = (size_t)(bS + r1g) * D_;
#pragma unroll
    for (int i = 0; i < 16; i++) {
        const int col = h * HD_ + i * 8 + qc;
        const float v0 = co[i][0] * inv0, v1 = co[i][1] * inv0;
        const float v2 = co[i][2] * inv1, v3 = co[i][3] * inv1;
        uint32_t h0 = pack_bf16(v0, v1);
        uint32_t h1 = pack_bf16(v2, v3);
        float2 f0 = unpack_bf16(h0), f1 = unpack_bf16(h1);
        uint32_t l0p = pack_bf16(v0 - f0.x, v1 - f0.y);
        uint32_t l1p = pack_bf16(v2 - f1.x, v3 - f1.y);
        *(uint32_t*)(g_AOhi + row0 + col) = h0;
        *(uint32_t*)(g_AOlo + row0 + col) = l0p;
        *(uint32_t*)(g_AOhi + row1 + col) = h1;
        *(uint32_t*)(g_AOlo + row1 + col) = l1p;
    }
}

// ============================================================================
// Launch
// ============================================================================
extern "C" void kernel_launch(void* const* d_in, const int* in_sizes, int n_in,
                              void* d_out, int out_size)
{
    const float* X  = (const float*)d_in[0];
    const int*   am = (const int*)  d_in[1];
    const float* Wq = (const float*)d_in[2];
    const float* Wk = (const float*)d_in[3];
    const float* Wv = (const float*)d_in[4];
    const float* Wo = (const float*)d_in[5];
    const float* bo = (const float*)d_in[6];
    float* out = (float*)d_out;

    void *Xhi, *Xlo, *AOhi, *AOlo;
    void *Qh, *Ql, *Kh, *Kl, *Vh, *Vl;
    void *Wqh, *Wql, *Wkh, *Wkl, *Wvh, *Wvl, *Woh, *Wol;
    cudaGetSymbolAddress(&Xhi,  g_Xhi);    cudaGetSymbolAddress(&Xlo,  g_Xlo);
    cudaGetSymbolAddress(&AOhi, g_AOhi);   cudaGetSymbolAddress(&AOlo, g_AOlo);
    cudaGetSymbolAddress(&Qh,   g_Qhi);    cudaGetSymbolAddress(&Ql,   g_Qlo);
    cudaGetSymbolAddress(&Kh,   g_Khi);    cudaGetSymbolAddress(&Kl,   g_Klo);
    cudaGetSymbolAddress(&Vh,   g_Vhi);    cudaGetSymbolAddress(&Vl,   g_Vlo);
    cudaGetSymbolAddress(&Wqh,  g_Wqt_hi); cudaGetSymbolAddress(&Wql,  g_Wqt_lo);
    cudaGetSymbolAddress(&Wkh,  g_Wkt_hi); cudaGetSymbolAddress(&Wkl,  g_Wkt_lo);
    cudaGetSymbolAddress(&Wvh,  g_Wvt_hi); cudaGetSymbolAddress(&Wvl,  g_Wvt_lo);
    cudaGetSymbolAddress(&Woh,  g_Wot_hi); cudaGetSymbolAddress(&Wol,  g_Wot_lo);

    cudaFuncSetAttribute(gemm_bf16x3,
        cudaFuncAttributeMaxDynamicSharedMemorySize, GEMM_SMEM);
    cudaFuncSetAttribute(attn_mma,
        cudaFuncAttributeMaxDynamicSharedMemorySize, ATT_SMEM);

    // ---- conversions ----
    const int n4 = (MTOT_ * D_) / 4;
    split_f32x4<<<(n4 + 255) / 256, 256>>>(
        (const float4*)X, (__nv_bfloat162*)Xhi, (__nv_bfloat162*)Xlo, n4);
    transpose_split4<<<dim3(D_ / 32, D_ / 32, 4), dim3(32, 8)>>>(
        Wq, Wk, Wv, Wo,
        (__nv_bfloat16*)Wqh, (__nv_bfloat16*)Wql,
        (__nv_bfloat16*)Wkh, (__nv_bfloat16*)Wkl,
        (__nv_bfloat16*)Wvh, (__nv_bfloat16*)Wvl,
        (__nv_bfloat16*)Woh, (__nv_bfloat16*)Wol);

    // ---- merged Q/K/V GEMM (split bf16 epilogue) ----
    G3 gqkv;
    gqkv.Ah  = (const __nv_bfloat16*)Xhi;  gqkv.Al  = (const __nv_bfloat16*)Xlo;
    gqkv.Bh0 = (const __nv_bfloat16*)Wqh;  gqkv.Bl0 = (const __nv_bfloat16*)Wql;
    gqkv.Bh1 = (const __nv_bfloat16*)Wkh;  gqkv.Bl1 = (const __nv_bfloat16*)Wkl;
    gqkv.Bh2 = (const __nv_bfloat16*)Wvh;  gqkv.Bl2 = (const __nv_bfloat16*)Wvl;
    gqkv.Ch0 = (__nv_bfloat16*)Qh; gqkv.Cl0 = (__nv_bfloat16*)Ql;
    gqkv.Ch1 = (__nv_bfloat16*)Kh; gqkv.Cl1 = (__nv_bfloat16*)Kl;
    gqkv.Ch2 = (__nv_bfloat16*)Vh; gqkv.Cl2 = (__nv_bfloat16*)Vl;
    gqkv.Cf = nullptr; gqkv.bias = nullptr;
    gemm_bf16x3<<<dim3(D_ / 128, MTOT_ / 128, 3), 256, GEMM_SMEM>>>(gqkv);

    // ---- tensor-core attention -> AOhi/AOlo ----
    attn_mma<<<dim3(S_ / 64, B_ * H_), 128, ATT_SMEM>>>(am);

    // ---- O GEMM (fp32 + bias) ----
    G3 go;
    go.Ah  = (const __nv_bfloat16*)AOhi; go.Al  = (const __nv_bfloat16*)AOlo;
    go.Bh0 = (const __nv_bfloat16*)Woh;  go.Bl0 = (const __nv_bfloat16*)Wol;
    go.Bh1 = go.Bh0; go.Bl1 = go.Bl0; go.Bh2 = go.Bh0; go.Bl2 = go.Bl0;
    go.Ch0 = nullptr; go.Cl0 = nullptr; go.Ch1 = nullptr; go.Cl1 = nullptr;
    go.Ch2 = nullptr; go.Cl2 = nullptr;
    go.Cf = out; go.bias = bo;
    gemm_bf16x3<<<dim3(D_ / 128, MTOT_ / 128, 1), 256, GEMM_SMEM>>>(go);
}

// round 6
// speedup vs baseline: 3.5818x; 1.0454x over previous
#include <cuda_runtime.h>
#include <cuda_bf16.h>
#include <cstdint>

#define B_ 2
#define S_ 2048
#define D_ 2048
#define H_ 16
#define HD_ 128
#define WINDOW_ 256
#define MTOT_ (B_ * S_)     // 4096
#define KDIM_ D_            // 2048

// -------- scratch (static __device__ arrays; no runtime allocation) --------
__device__ __align__(1024) __nv_bfloat16 g_Xhi [(size_t)MTOT_ * D_];
__device__ __align__(1024) __nv_bfloat16 g_Xlo [(size_t)MTOT_ * D_];
__device__ __align__(1024) __nv_bfloat16 g_Qhi [(size_t)MTOT_ * D_];
__device__ __align__(1024) __nv_bfloat16 g_Qlo [(size_t)MTOT_ * D_];
__device__ __align__(1024) __nv_bfloat16 g_Khi [(size_t)MTOT_ * D_];
__device__ __align__(1024) __nv_bfloat16 g_Klo [(size_t)MTOT_ * D_];
__device__ __align__(1024) __nv_bfloat16 g_Vhi [(size_t)MTOT_ * D_];
__device__ __align__(1024) __nv_bfloat16 g_Vlo [(size_t)MTOT_ * D_];
__device__ __align__(1024) __nv_bfloat16 g_AOhi[(size_t)MTOT_ * D_];
__device__ __align__(1024) __nv_bfloat16 g_AOlo[(size_t)MTOT_ * D_];
__device__ __align__(1024) __nv_bfloat16 g_Wqt_hi[(size_t)D_ * D_];
__device__ __align__(1024) __nv_bfloat16 g_Wqt_lo[(size_t)D_ * D_];
__device__ __align__(1024) __nv_bfloat16 g_Wkt_hi[(size_t)D_ * D_];
__device__ __align__(1024) __nv_bfloat16 g_Wkt_lo[(size_t)D_ * D_];
__device__ __align__(1024) __nv_bfloat16 g_Wvt_hi[(size_t)D_ * D_];
__device__ __align__(1024) __nv_bfloat16 g_Wvt_lo[(size_t)D_ * D_];
__device__ __align__(1024) __nv_bfloat16 g_Wot_hi[(size_t)D_ * D_];
__device__ __align__(1024) __nv_bfloat16 g_Wot_lo[(size_t)D_ * D_];

// ============================================================================
// helpers (generic PTX only — sm_80-compatible, safe for compute_103)
// ============================================================================
__device__ __forceinline__ uint32_t smem_u32(const void* p) {
    uint32_t a;
    asm("{ .reg .u64 t; cvta.to.shared.u64 t, %1; cvt.u32.u64 %0, t; }"
        : "=r"(a) : "l"(p));
    return a;
}

#define SWZ(o) ((o) ^ (((o) >> 3) & 0x70))
// packed rows: two 64B logical rows per 128B swizzled line
#define PKOFF(row, b) SWZ((((row) >> 1) << 7) + (((row) & 1) << 6) + (b))

#define CP_ASYNC16(dst, src) \
    asm volatile("cp.async.cg.shared.global [%0], [%1], 16;" \
                 :: "r"(dst), "l"(src) : "memory")
#define CP_COMMIT() asm volatile("cp.async.commit_group;" ::: "memory")
#define CP_WAIT0()  asm volatile("cp.async.wait_group 0;" ::: "memory")
#define CP_WAIT1()  asm volatile("cp.async.wait_group 1;" ::: "memory")

#define LDSM_X4(rr, addr) \
    asm volatile("ldmatrix.sync.aligned.m8n8.x4.shared.b16 {%0,%1,%2,%3}, [%4];" \
        : "=r"((rr)[0]), "=r"((rr)[1]), "=r"((rr)[2]), "=r"((rr)[3]) : "r"(addr))

#define LDSM_X4_T(rr, addr) \
    asm volatile("ldmatrix.sync.aligned.m8n8.x4.trans.shared.b16 {%0,%1,%2,%3}, [%4];" \
        : "=r"((rr)[0]), "=r"((rr)[1]), "=r"((rr)[2]), "=r"((rr)[3]) : "r"(addr))

#define MMA_BF16(cc, aa, b0, b1) \
    asm volatile("mma.sync.aligned.m16n8k16.row.col.f32.bf16.bf16.f32 " \
        "{%0,%1,%2,%3}, {%4,%5,%6,%7}, {%8,%9}, {%0,%1,%2,%3};" \
        : "+f"((cc)[0]), "+f"((cc)[1]), "+f"((cc)[2]), "+f"((cc)[3]) \
        : "r"((aa)[0]), "r"((aa)[1]), "r"((aa)[2]), "r"((aa)[3]), \
          "r"(b0), "r"(b1))

// pack two f32 into bf16x2: low half = lo, high half = hi
__device__ __forceinline__ uint32_t pack_bf16(float lo, float hi) {
    uint32_t r;
    asm("cvt.rn.bf16x2.f32 %0, %1, %2;" : "=r"(r) : "f"(hi), "f"(lo));
    return r;
}
__device__ __forceinline__ float2 unpack_bf16(uint32_t u) {
    __nv_bfloat162 b = *reinterpret_cast<__nv_bfloat162*>(&u);
    return make_float2(__bfloat162float(b.x), __bfloat162float(b.y));
}

// ============================================================================
// bf16 3-split GEMM via mma.sync: 128x128 CTA tile, 4 warps (64x64 each),
// BK=32 packed-row layout, 3-stage cp.async pipeline, 2 CTAs/SM.
// D = Ah*Bh + Ah*Bl + Al*Bh (fp32 accum).
// ============================================================================
#define TILE_B2 8192       // one 128x32 bf16 tile (packed rows)
#define STAGE_B 32768      // Ah|Al|Bh|Bl
#define NCHUNKS 64         // K / 32
#define GEMM_SMEM (3 * STAGE_B)   // 98304 -> 2 CTAs/SM

struct G3 {
    const __nv_bfloat16 *Ah, *Al;
    const __nv_bfloat16 *Bh0, *Bl0, *Bh1, *Bl1, *Bh2, *Bl2;
    __nv_bfloat16 *Ch0, *Cl0, *Ch1, *Cl1, *Ch2, *Cl2;   // split outputs
    float* Cf;                                           // fp32 output
    const float* bias;
};

__device__ __forceinline__ void issue_chunk(
    const __nv_bfloat16* Ah, const __nv_bfloat16* Al,
    const __nv_bfloat16* Bh, const __nv_bfloat16* Bl,
    int t, int tid, int m0, int n0, uint32_t sb)
{
    const int k0 = t << 5;   // BK = 32
    const uint32_t stg = sb + (t % 3) * STAGE_B;
#pragma unroll
    for (int v = 0; v < 16; v++) {
        const int tile = v >> 2;               // 0=Ah 1=Al 2=Bh 3=Bl
        const int slot = ((v & 3) << 7) + tid; // 0..511
        const int row  = slot >> 2;            // 0..127
        const int c16  = slot & 3;             // 0..3 (16B within 64B row)
        const uint32_t dst = stg + (tile << 13) + PKOFF(row, c16 * 16);
        const __nv_bfloat16* base =
            (tile == 0) ? Ah : (tile == 1) ? Al : (tile == 2) ? Bh : Bl;
        const int r0 = (tile < 2) ? m0 : n0;
        CP_ASYNC16(dst, (const char*)(base + (size_t)(r0 + row) * KDIM_ + k0)
                        + c16 * 16);
    }
}

__global__ __launch_bounds__(128, 2)
void gemm_bf16x3(G3 ga)
{
    extern __shared__ __align__(1024) char smg[];
    const uint32_t sb = smem_u32(smg);
    const int tid = threadIdx.x;
    const int wid = tid >> 5, lid = tid & 31;
    const int warp_m = wid & 1;        // 0..1 (64 rows)
    const int warp_n = wid >> 1;       // 0..1 (64 cols)
    const int m0 = blockIdx.y << 7;
    const int n0 = blockIdx.x << 7;
    const int z  = blockIdx.z;

    const __nv_bfloat16* Bh = (z == 0) ? ga.Bh0 : (z == 1) ? ga.Bh1 : ga.Bh2;
    const __nv_bfloat16* Bl = (z == 0) ? ga.Bl0 : (z == 1) ? ga.Bl1 : ga.Bl2;

    const int grp = lid >> 3;
    const int lr  = lid & 7;

    float c[4][8][4];
#pragma unroll
    for (int mt = 0; mt < 4; mt++)
#pragma unroll
        for (int nt = 0; nt < 8; nt++)
#pragma unroll
            for (int q = 0; q < 4; q++) c[mt][nt][q] = 0.f;

    const int a_row = warp_m * 64 + (grp & 1) * 8 + lr;   // + mt*16
    const int a_kb  = (grp >> 1) * 16;                    // + kt*32
    const int b_row = warp_n * 64 + (grp >> 1) * 8 + lr;  // + nb*16
    const int b_kb  = (grp & 1) * 16;                     // + kt*32

    issue_chunk(ga.Ah, ga.Al, Bh, Bl, 0, tid, m0, n0, sb); CP_COMMIT();
    issue_chunk(ga.Ah, ga.Al, Bh, Bl, 1, tid, m0, n0, sb); CP_COMMIT();

    for (int t = 0; t < NCHUNKS; t++) {
        CP_WAIT1();
        __syncthreads();
        if (t + 2 < NCHUNKS)
            issue_chunk(ga.Ah, ga.Al, Bh, Bl, t + 2, tid, m0, n0, sb);
        CP_COMMIT();

        const uint32_t Ahs = sb + (t % 3) * STAGE_B;
        const uint32_t Als = Ahs + TILE_B2;
        const uint32_t Bhs = Ahs + 2 * TILE_B2;
        const uint32_t Bls = Ahs + 3 * TILE_B2;

#pragma unroll
        for (int kt = 0; kt < 2; kt++) {
            uint32_t bh[4][4], bl[4][4];
#pragma unroll
            for (int nb = 0; nb < 4; nb++) {
                const uint32_t bo = PKOFF(b_row + nb * 16, kt * 32 + b_kb);
                LDSM_X4(bh[nb], Bhs + bo);
                LDSM_X4(bl[nb], Bls + bo);
            }
#pragma unroll
            for (int mt = 0; mt < 4; mt++) {
                uint32_t ah[4], al[4];
                const uint32_t ao = PKOFF(a_row + mt * 16, kt * 32 + a_kb);
                LDSM_X4(ah, Ahs + ao);
                LDSM_X4(al, Als + ao);
#pragma unroll
                for (int nb = 0; nb < 4; nb++) {
                    MMA_BF16(c[mt][2 * nb],     ah, bh[nb][0], bh[nb][1]);
                    MMA_BF16(c[mt][2 * nb + 1], ah, bh[nb][2], bh[nb][3]);
                    MMA_BF16(c[mt][2 * nb],     ah, bl[nb][0], bl[nb][1]);
                    MMA_BF16(c[mt][2 * nb + 1], ah, bl[nb][2], bl[nb][3]);
                    MMA_BF16(c[mt][2 * nb],     al, bh[nb][0], bh[nb][1]);
                    MMA_BF16(c[mt][2 * nb + 1], al, bh[nb][2], bh[nb][3]);
                }
            }
        }
        __syncthreads();
    }

    // ---- epilogue ----
    const int l4 = lid >> 2;
    const int l2 = (lid & 3) << 1;
    if (ga.Cf) {
        float* C = ga.Cf;
#pragma unroll
        for (int mt = 0; mt < 4; mt++) {
            const int row = m0 + warp_m * 64 + mt * 16 + l4;
#pragma unroll
            for (int nt = 0; nt < 8; nt++) {
                const int col = n0 + warp_n * 64 + nt * 8 + l2;
                float2 v0 = make_float2(c[mt][nt][0], c[mt][nt][1]);
                float2 v1 = make_float2(c[mt][nt][2], c[mt][nt][3]);
                const float b0 = ga.bias[col], b1 = ga.bias[col + 1];
                v0.x += b0; v0.y += b1;
                v1.x += b0; v1.y += b1;
                *(float2*)(C + (size_t)row * D_ + col)       = v0;
                *(float2*)(C + (size_t)(row + 8) * D_ + col) = v1;
            }
        }
    } else {
        __nv_bfloat16* Ch = (z == 0) ? ga.Ch0 : (z == 1) ? ga.Ch1 : ga.Ch2;
        __nv_bfloat16* Cl = (z == 0) ? ga.Cl0 : (z == 1) ? ga.Cl1 : ga.Cl2;
#pragma unroll
        for (int mt = 0; mt < 4; mt++) {
            const int row = m0 + warp_m * 64 + mt * 16 + l4;
#pragma unroll
            for (int nt = 0; nt < 8; nt++) {
                const int col = n0 + warp_n * 64 + nt * 8 + l2;
                const size_t o0 = (size_t)row * D_ + col;
                const size_t o1 = (size_t)(row + 8) * D_ + col;
                uint32_t h0 = pack_bf16(c[mt][nt][0], c[mt][nt][1]);
                uint32_t h1 = pack_bf16(c[mt][nt][2], c[mt][nt][3]);
                float2 f0 = unpack_bf16(h0), f1 = unpack_bf16(h1);
                uint32_t l0p = pack_bf16(c[mt][nt][0] - f0.x, c[mt][nt][1] - f0.y);
                uint32_t l1p = pack_bf16(c[mt][nt][2] - f1.x, c[mt][nt][3] - f1.y);
                *(uint32_t*)(Ch + o0) = h0;
                *(uint32_t*)(Ch + o1) = h1;
                *(uint32_t*)(Cl + o0) = l0p;
                *(uint32_t*)(Cl + o1) = l1p;
            }
        }
    }
}

// ============================================================================
// fp32 -> (hi, lo) bf16 split, elementwise (vectorized x4)
// ============================================================================
__global__ void split_f32x4(const float4* __restrict__ in,
                            __nv_bfloat162* __restrict__ hi,
                            __nv_bfloat162* __restrict__ lo, int n4)
{
    int i = blockIdx.x * blockDim.x + threadIdx.x;
    if (i >= n4) return;
    float4 x = in[i];
    __nv_bfloat16 h0 = __float2bfloat16(x.x);
    __nv_bfloat16 h1 = __float2bfloat16(x.y);
    __nv_bfloat16 h2 = __float2bfloat16(x.z);
    __nv_bfloat16 h3 = __float2bfloat16(x.w);
    __nv_bfloat16 l0 = __float2bfloat16(x.x - __bfloat162float(h0));
    __nv_bfloat16 l1 = __float2bfloat16(x.y - __bfloat162float(h1));
    __nv_bfloat16 l2 = __float2bfloat16(x.z - __bfloat162float(h2));
    __nv_bfloat16 l3 = __float2bfloat16(x.w - __bfloat162float(h3));
    hi[2 * i]     = __halves2bfloat162(h0, h1);
    hi[2 * i + 1] = __halves2bfloat162(h2, h3);
    lo[2 * i]     = __halves2bfloat162(l0, l1);
    lo[2 * i + 1] = __halves2bfloat162(l2, l3);
}

// ============================================================================
// W[K, N] fp32 -> Wt_hi/lo[N, K] bf16 (transpose + split); z selects matrix
// ============================================================================
__global__ void transpose_split4(const float* __restrict__ W0,
                                 const float* __restrict__ W1,
                                 const float* __restrict__ W2,
                                 const float* __restrict__ W3,
                                 __nv_bfloat16* __restrict__ h0, __nv_bfloat16* __restrict__ l0,
                                 __nv_bfloat16* __restrict__ h1, __nv_bfloat16* __restrict__ l1,
                                 __nv_bfloat16* __restrict__ h2, __nv_bfloat16* __restrict__ l2,
                                 __nv_bfloat16* __restrict__ h3, __nv_bfloat16* __restrict__ l3)
{
    const int z = blockIdx.z;
    const float* W = (z == 0) ? W0 : (z == 1) ? W1 : (z == 2) ? W2 : W3;
    __nv_bfloat16* hi = (z == 0) ? h0 : (z == 1) ? h1 : (z == 2) ? h2 : h3;
    __nv_bfloat16* lo = (z == 0) ? l0 : (z == 1) ? l1 : (z == 2) ? l2 : l3;

    __shared__ float t[32][33];
    const int kt = blockIdx.y * 32, nt = blockIdx.x * 32;
    const int tx = threadIdx.x, ty = threadIdx.y;
#pragma unroll
    for (int i = 0; i < 32; i += 8)
        t[ty + i][tx] = W[(size_t)(kt + ty + i) * D_ + nt + tx];
    __syncthreads();
#pragma unroll
    for (int i = 0; i < 32; i += 8) {
        const float x = t[tx][ty + i];
        const size_t o = (size_t)(nt + ty + i) * KDIM_ + kt + tx;
        __nv_bfloat16 h = __float2bfloat16(x);
        hi[o] = h;
        lo[o] = __float2bfloat16(x - __bfloat162float(h));
    }
}

// ============================================================================
// Tensor-core banded attention (unchanged from R5, 97us)
// ============================================================================
#define AQHI 0
#define AQLO 16384
#define AKHI 32768
#define AKLO 49152
#define AVHI 65536
#define AVLO 81920
#define AAM  98304
#define ATT_SMEM (98304 + 256)

__device__ __forceinline__ void load64x128(uint32_t dst, const __nv_bfloat16* src, int tid)
{
#pragma unroll
    for (int v = 0; v < 8; v++) {
        const int idx = (v << 7) + tid;
        const int row = idx >> 4;
        const int c16 = idx & 15;
        CP_ASYNC16(dst + ((c16 >> 3) << 13) + SWZ(row * 128 + (c16 & 7) * 16),
                   (const char*)(src + (size_t)row * D_) + c16 * 16);
    }
}

__global__ __launch_bounds__(128)
void attn_mma(const int* __restrict__ amask)
{
    extern __shared__ __align__(1024) char sma[];
    const uint32_t sb = smem_u32(sma);
    int* am_s = (int*)(sma + AAM);

    const int tid = threadIdx.x;
    const int w   = tid >> 5;
    const int lid = tid & 31;
    const int b   = blockIdx.y >> 4;
    const int h   = blockIdx.y & 15;
    const int q0  = blockIdx.x << 6;
    const int bS  = b * S_;

    const int grp = lid >> 3, lr = lid & 7;
    const int qr  = lid >> 2;
    const int qc  = (lid & 3) << 1;

    const size_t qoff = (size_t)(bS + q0) * D_ + h * HD_;
    load64x128(sb + AQHI, g_Qhi + qoff, tid);
    load64x128(sb + AQLO, g_Qlo + qoff, tid);
    int kbeg = q0 - WINDOW_;
    if (kbeg < 0) kbeg = 0;
    const int nch = ((q0 - kbeg) >> 6) + 1;
    const size_t koff0 = (size_t)(bS + kbeg) * D_ + h * HD_;
    load64x128(sb + AKHI, g_Khi + koff0, tid);
    load64x128(sb + AKLO, g_Klo + koff0, tid);
    CP_COMMIT();
    load64x128(sb + AVHI, g_Vhi + koff0, tid);
    load64x128(sb + AVLO, g_Vlo + koff0, tid);
    CP_COMMIT();

    float m0 = -1e30f, m1 = -1e30f, l0 = 0.f, l1 = 0.f;
    float co[16][4];
#pragma unroll
    for (int i = 0; i < 16; i++)
#pragma unroll
        for (int q = 0; q < 4; q++) co[i][q] = 0.f;

    const int r0g = q0 + w * 16 + qr;
    const int r1g = r0g + 8;

    const int arow = w * 16 + (grp & 1) * 8 + lr;
    const int brow = (grp >> 1) * 8 + lr;

    for (int ci = 0; ci < nch; ci++) {
        const int k0 = kbeg + (ci << 6);
        if (tid < 64) am_s[tid] = amask[bS + k0 + tid];
        CP_WAIT1();
        __syncthreads();

        float cs[8][4];
#pragma unroll
        for (int nt = 0; nt < 8; nt++)
#pragma unroll
            for (int q = 0; q < 4; q++) cs[nt][q] = 0.f;

#pragma unroll
        for (int ks = 0; ks < 8; ks++) {
            const uint32_t ao = ((ks >> 2) << 13)
                              + SWZ(arow * 128 + (ks & 3) * 32 + (grp >> 1) * 16);
            uint32_t ah[4], al[4];
            LDSM_X4(ah, sb + AQHI + ao);
            LDSM_X4(al, sb + AQLO + ao);
            const uint32_t bw = (ks & 3) * 32 + (grp & 1) * 16;
#pragma unroll
            for (int nb = 0; nb < 4; nb++) {
                const uint32_t bo = ((ks >> 2) << 13)
                                  + SWZ((brow + nb * 16) * 128 + bw);
                uint32_t bh[4], bl[4];
                LDSM_X4(bh, sb + AKHI + bo);
                LDSM_X4(bl, sb + AKLO + bo);
                MMA_BF16(cs[2 * nb],     ah, bh[0], bh[1]);
                MMA_BF16(cs[2 * nb + 1], ah, bh[2], bh[3]);
                MMA_BF16(cs[2 * nb],     ah, bl[0], bl[1]);
                MMA_BF16(cs[2 * nb + 1], ah, bl[2], bl[3]);
                MMA_BF16(cs[2 * nb],     al, bh[0], bh[1]);
                MMA_BF16(cs[2 * nb + 1], al, bh[2], bh[3]);
            }
        }

#pragma unroll
        for (int nt = 0; nt < 8; nt++) {
            const int cl = nt * 8 + qc;
            const int c0 = k0 + cl, c1 = c0 + 1;
            const int am0 = am_s[cl], am1 = am_s[cl + 1];
            if (!(c0 <= r0g && r0g - c0 < WINDOW_ && am0)) cs[nt][0] = -1e30f;
            if (!(c1 <= r0g && r0g - c1 < WINDOW_ && am1)) cs[nt][1] = -1e30f;
            if (!(c0 <= r1g && r1g - c0 < WINDOW_ && am0)) cs[nt][2] = -1e30f;
            if (!(c1 <= r1g && r1g - c1 < WINDOW_ && am1)) cs[nt][3] = -1e30f;
        }

        float mc0 = -1e30f, mc1 = -1e30f;
#pragma unroll
        for (int nt = 0; nt < 8; nt++) {
            mc0 = fmaxf(mc0, fmaxf(cs[nt][0], cs[nt][1]));
            mc1 = fmaxf(mc1, fmaxf(cs[nt][2], cs[nt][3]));
        }
        mc0 = fmaxf(mc0, __shfl_xor_sync(0xffffffffu, mc0, 1));
        mc0 = fmaxf(mc0, __shfl_xor_sync(0xffffffffu, mc0, 2));
        mc1 = fmaxf(mc1, __shfl_xor_sync(0xffffffffu, mc1, 1));
        mc1 = fmaxf(mc1, __shfl_xor_sync(0xffffffffu, mc1, 2));
        const float mn0 = fmaxf(m0, mc0), mn1 = fmaxf(m1, mc1);
        const float sc0 = __expf(m0 - mn0), sc1 = __expf(m1 - mn1);

        float ls0 = 0.f, ls1 = 0.f;
#pragma unroll
        for (int nt = 0; nt < 8; nt++) {
            cs[nt][0] = (cs[nt][0] > -1e29f) ? __expf(cs[nt][0] - mn0) : 0.f;
            cs[nt][1] = (cs[nt][1] > -1e29f) ? __expf(cs[nt][1] - mn0) : 0.f;
            cs[nt][2] = (cs[nt][2] > -1e29f) ? __expf(cs[nt][2] - mn1) : 0.f;
            cs[nt][3] = (cs[nt][3] > -1e29f) ? __expf(cs[nt][3] - mn1) : 0.f;
            ls0 += cs[nt][0] + cs[nt][1];
            ls1 += cs[nt][2] + cs[nt][3];
        }
        ls0 += __shfl_xor_sync(0xffffffffu, ls0, 1);
        ls0 += __shfl_xor_sync(0xffffffffu, ls0, 2);
        ls1 += __shfl_xor_sync(0xffffffffu, ls1, 1);
        ls1 += __shfl_xor_sync(0xffffffffu, ls1, 2);
        l0 = l0 * sc0 + ls0;
        l1 = l1 * sc1 + ls1;
#pragma unroll
        for (int i = 0; i < 16; i++) {
            co[i][0] *= sc0; co[i][1] *= sc0;
            co[i][2] *= sc1; co[i][3] *= sc1;
        }
        m0 = mn0; m1 = mn1;

        CP_WAIT0();
        __syncthreads();
        if (ci + 1 < nch) {
            const size_t kn = (size_t)(bS + k0 + 64) * D_ + h * HD_;
            load64x128(sb + AKHI, g_Khi + kn, tid);
            load64x128(sb + AKLO, g_Klo + kn, tid);
            CP_COMMIT();
        }

#pragma unroll
        for (int ks = 0; ks < 4; ks++) {
            uint32_t phi[4], plo[4];
            phi[0] = pack_bf16(cs[2 * ks][0],     cs[2 * ks][1]);
            phi[1] = pack_bf16(cs[2 * ks][2],     cs[2 * ks][3]);
            phi[2] = pack_bf16(cs[2 * ks + 1][0], cs[2 * ks + 1][1]);
            phi[3] = pack_bf16(cs[2 * ks + 1][2], cs[2 * ks + 1][3]);
            {
                float2 f0 = unpack_bf16(phi[0]);
                float2 f1 = unpack_bf16(phi[1]);
                float2 f2 = unpack_bf16(phi[2]);
                float2 f3 = unpack_bf16(phi[3]);
                plo[0] = pack_bf16(cs[2*ks][0]   - f0.x, cs[2*ks][1]   - f0.y);
                plo[1] = pack_bf16(cs[2*ks][2]   - f1.x, cs[2*ks][3]   - f1.y);
                plo[2] = pack_bf16(cs[2*ks+1][0] - f2.x, cs[2*ks+1][1] - f2.y);
                plo[3] = pack_bf16(cs[2*ks+1][2] - f3.x, cs[2*ks+1][3] - f3.y);
            }
            const int vrow = ks * 16 + (grp & 1) * 8 + lr;
            const uint32_t vw = (grp >> 1) * 16;
#pragma unroll
            for (int g2 = 0; g2 < 8; g2++) {
                const uint32_t vo = ((g2 >> 2) << 13)
                                  + SWZ(vrow * 128 + (g2 & 3) * 32 + vw);
                uint32_t vh[4], vl[4];
                LDSM_X4_T(vh, sb + AVHI + vo);
                LDSM_X4_T(vl, sb + AVLO + vo);
                MMA_BF16(co[2 * g2],     phi, vh[0], vh[1]);
                MMA_BF16(co[2 * g2 + 1], phi, vh[2], vh[3]);
                MMA_BF16(co[2 * g2],     phi, vl[0], vl[1]);
                MMA_BF16(co[2 * g2 + 1], phi, vl[2], vl[3]);
                MMA_BF16(co[2 * g2],     plo, vh[0], vh[1]);
                MMA_BF16(co[2 * g2 + 1], plo, vh[2], vh[3]);
            }
        }
        __syncthreads();
        if (ci + 1 < nch) {
            const size_t vn = (size_t)(bS + k0 + 64) * D_ + h * HD_;
            load64x128(sb + AVHI, g_Vhi + vn, tid);
            load64x128(sb + AVLO, g_Vlo + vn, tid);
            CP_COMMIT();
        }
    }

    const float inv0 = (l0 > 0.f) ? (1.f / l0) : 0.f;
    const float inv1 = (l1 > 0.f) ? (1.f / l1) : 0.f;
    const size_t row0 = (size_t)(bS + r0g) * D_;
    const size_t row1 = (size_t)(bS + r1g) * D_;
#pragma unroll
    for (int i = 0; i < 16; i++) {
        const int col = h * HD_ + i * 8 + qc;
        const float v0 = co[i][0] * inv0, v1 = co[i][1] * inv0;
        const float v2 = co[i][2] * inv1, v3 = co[i][3] * inv1;
        uint32_t h0 = pack_bf16(v0, v1);
        uint32_t h1 = pack_bf16(v2, v3);
        float2 f0 = unpack_bf16(h0), f1 = unpack_bf16(h1);
        uint32_t l0p = pack_bf16(v0 - f0.x, v1 - f0.y);
        uint32_t l1p = pack_bf16(v2 - f1.x, v3 - f1.y);
        *(uint32_t*)(g_AOhi + row0 + col) = h0;
        *(uint32_t*)(g_AOlo + row0 + col) = l0p;
        *(uint32_t*)(g_AOhi + row1 + col) = h1;
        *(uint32_t*)(g_AOlo + row1 + col) = l1p;
    }
}

// ============================================================================
// Launch
// ============================================================================
extern "C" void kernel_launch(void* const* d_in, const int* in_sizes, int n_in,
                              void* d_out, int out_size)
{
    const float* X  = (const float*)d_in[0];
    const int*   am = (const int*)  d_in[1];
    const float* Wq = (const float*)d_in[2];
    const float* Wk = (const float*)d_in[3];
    const float* Wv = (const float*)d_in[4];
    const float* Wo = (const float*)d_in[5];
    const float* bo = (const float*)d_in[6];
    float* out = (float*)d_out;

    void *Xhi, *Xlo, *AOhi, *AOlo;
    void *Qh, *Ql, *Kh, *Kl, *Vh, *Vl;
    void *Wqh, *Wql, *Wkh, *Wkl, *Wvh, *Wvl, *Woh, *Wol;
    cudaGetSymbolAddress(&Xhi,  g_Xhi);    cudaGetSymbolAddress(&Xlo,  g_Xlo);
    cudaGetSymbolAddress(&AOhi, g_AOhi);   cudaGetSymbolAddress(&AOlo, g_AOlo);
    cudaGetSymbolAddress(&Qh,   g_Qhi);    cudaGetSymbolAddress(&Ql,   g_Qlo);
    cudaGetSymbolAddress(&Kh,   g_Khi);    cudaGetSymbolAddress(&Kl,   g_Klo);
    cudaGetSymbolAddress(&Vh,   g_Vhi);    cudaGetSymbolAddress(&Vl,   g_Vlo);
    cudaGetSymbolAddress(&Wqh,  g_Wqt_hi); cudaGetSymbolAddress(&Wql,  g_Wqt_lo);
    cudaGetSymbolAddress(&Wkh,  g_Wkt_hi); cudaGetSymbolAddress(&Wkl,  g_Wkt_lo);
    cudaGetSymbolAddress(&Wvh,  g_Wvt_hi); cudaGetSymbolAddress(&Wvl,  g_Wvt_lo);
    cudaGetSymbolAddress(&Woh,  g_Wot_hi); cudaGetSymbolAddress(&Wol,  g_Wot_lo);

    cudaFuncSetAttribute(gemm_bf16x3,
        cudaFuncAttributeMaxDynamicSharedMemorySize, GEMM_SMEM);
    cudaFuncSetAttribute(attn_mma,
        cudaFuncAttributeMaxDynamicSharedMemorySize, ATT_SMEM);

    // ---- conversions ----
    const int n4 = (MTOT_ * D_) / 4;
    split_f32x4<<<(n4 + 255) / 256, 256>>>(
        (const float4*)X, (__nv_bfloat162*)Xhi, (__nv_bfloat162*)Xlo, n4);
    transpose_split4<<<dim3(D_ / 32, D_ / 32, 4), dim3(32, 8)>>>(
        Wq, Wk, Wv, Wo,
        (__nv_bfloat16*)Wqh, (__nv_bfloat16*)Wql,
        (__nv_bfloat16*)Wkh, (__nv_bfloat16*)Wkl,
        (__nv_bfloat16*)Wvh, (__nv_bfloat16*)Wvl,
        (__nv_bfloat16*)Woh, (__nv_bfloat16*)Wol);

    // ---- merged Q/K/V GEMM (split bf16 epilogue) ----
    G3 gqkv;
    gqkv.Ah  = (const __nv_bfloat16*)Xhi;  gqkv.Al  = (const __nv_bfloat16*)Xlo;
    gqkv.Bh0 = (const __nv_bfloat16*)Wqh;  gqkv.Bl0 = (const __nv_bfloat16*)Wql;
    gqkv.Bh1 = (const __nv_bfloat16*)Wkh;  gqkv.Bl1 = (const __nv_bfloat16*)Wkl;
    gqkv.Bh2 = (const __nv_bfloat16*)Wvh;  gqkv.Bl2 = (const __nv_bfloat16*)Wvl;
    gqkv.Ch0 = (__nv_bfloat16*)Qh; gqkv.Cl0 = (__nv_bfloat16*)Ql;
    gqkv.Ch1 = (__nv_bfloat16*)Kh; gqkv.Cl1 = (__nv_bfloat16*)Kl;
    gqkv.Ch2 = (__nv_bfloat16*)Vh; gqkv.Cl2 = (__nv_bfloat16*)Vl;
    gqkv.Cf = nullptr; gqkv.bias = nullptr;
    gemm_bf16x3<<<dim3(D_ / 128, MTOT_ / 128, 3), 128, GEMM_SMEM>>>(gqkv);

    // ---- tensor-core attention -> AOhi/AOlo ----
    attn_mma<<<dim3(S_ / 64, B_ * H_), 128, ATT_SMEM>>>(am);

    // ---- O GEMM (fp32 + bias) ----
    G3 go;
    go.Ah  = (const __nv_bfloat16*)AOhi; go.Al  = (const __nv_bfloat16*)AOlo;
    go.Bh0 = (const __nv_bfloat16*)Woh;  go.Bl0 = (const __nv_bfloat16*)Wol;
    go.Bh1 = go.Bh0; go.Bl1 = go.Bl0; go.Bh2 = go.Bh0; go.Bl2 = go.Bl0;
    go.Ch0 = nullptr; go.Cl0 = nullptr; go.Ch1 = nullptr; go.Cl1 = nullptr;
    go.Ch2 = nullptr; go.Cl2 = nullptr;
    go.Cf = out; go.bias = bo;
    gemm_bf16x3<<<dim3(D_ / 128, MTOT_ / 128, 1), 128, GEMM_SMEM>>>(go);
}